// round 1
// baseline (speedup 1.0000x reference)
#include <cuda_runtime.h>
#include <math.h>

#define S_LEN  4096
#define BATCH  2
#define NH     8
#define HD     32
#define EDIM   256
#define WIN    64

// ---- scratch (no allocations allowed; __device__ globals) ----
__device__ float g_Q[BATCH * NH * S_LEN * HD];   // 8 MB, pre-scaled by 1/sqrt(32)
__device__ float g_K[BATCH * NH * S_LEN * HD];   // 8 MB
__device__ float g_V[BATCH * NH * S_LEN * HD];   // 8 MB
__device__ float g_O[BATCH * S_LEN * EDIM];      // 8 MB, attention output in [B,S,E]

// ================= tiled SGEMM: C[M,N] = A[M,K] * B[N,K]^T + bias =================
// Both A and B are K-contiguous (NT gemm). BM=BN=128, BK=8, 256 threads, 8x8 micro-tile.
#define BM 128
#define BN 128
#define BKK 8
#define LDA (BM + 4)

// QKV_MODE==1: scatter epilogue into g_Q/g_K/g_V ([B,H,S,D] layout, Q scaled).
// QKV_MODE==0: plain epilogue into C (row-major [M,N]).
template <int QKV_MODE>
__global__ __launch_bounds__(256) void gemm_nt(
    const float* __restrict__ A, const float* __restrict__ Bm,
    const float* __restrict__ bias, float* __restrict__ C,
    int M, int N, int K)
{
    __shared__ float As[BKK * LDA];
    __shared__ float Bs[BKK * LDA];

    const int tid = threadIdx.x;
    const int tx = tid & 15;        // 0..15  -> N direction
    const int ty = tid >> 4;        // 0..15  -> M direction
    const int m0 = blockIdx.y * BM;
    const int n0 = blockIdx.x * BN;

    float acc[8][8];
#pragma unroll
    for (int i = 0; i < 8; i++)
#pragma unroll
        for (int j = 0; j < 8; j++) acc[i][j] = 0.f;

    const int lr = tid >> 1;              // 0..127 row within tile
    const int lk = (tid & 1) * 4;         // 0 or 4 (float4 within BK=8)

    const float* Arow = A + (size_t)(m0 + lr) * K + lk;
    const float* Brow = Bm + (size_t)(n0 + lr) * K + lk;

    for (int k0 = 0; k0 < K; k0 += BKK) {
        const float4 av = *reinterpret_cast<const float4*>(Arow + k0);
        const float4 bv = *reinterpret_cast<const float4*>(Brow + k0);
        __syncthreads();
        // transposed store: As[k][m]; conflict-free (132 % 32 == 4 pattern)
        As[(lk + 0) * LDA + lr] = av.x;
        As[(lk + 1) * LDA + lr] = av.y;
        As[(lk + 2) * LDA + lr] = av.z;
        As[(lk + 3) * LDA + lr] = av.w;
        Bs[(lk + 0) * LDA + lr] = bv.x;
        Bs[(lk + 1) * LDA + lr] = bv.y;
        Bs[(lk + 2) * LDA + lr] = bv.z;
        Bs[(lk + 3) * LDA + lr] = bv.w;
        __syncthreads();

#pragma unroll
        for (int kk = 0; kk < BKK; kk++) {
            float a[8], b[8];
            *reinterpret_cast<float4*>(&a[0]) = *reinterpret_cast<const float4*>(&As[kk * LDA + ty * 8]);
            *reinterpret_cast<float4*>(&a[4]) = *reinterpret_cast<const float4*>(&As[kk * LDA + ty * 8 + 4]);
            *reinterpret_cast<float4*>(&b[0]) = *reinterpret_cast<const float4*>(&Bs[kk * LDA + tx * 8]);
            *reinterpret_cast<float4*>(&b[4]) = *reinterpret_cast<const float4*>(&Bs[kk * LDA + tx * 8 + 4]);
#pragma unroll
            for (int i = 0; i < 8; i++)
#pragma unroll
                for (int j = 0; j < 8; j++)
                    acc[i][j] = fmaf(a[i], b[j], acc[i][j]);
        }
    }

    if (QKV_MODE == 0) {
#pragma unroll
        for (int i = 0; i < 8; i++) {
            const int row = m0 + ty * 8 + i;
            float* crow = C + (size_t)row * N + n0 + tx * 8;
#pragma unroll
            for (int j = 0; j < 8; j += 4) {
                float4 o;
                o.x = acc[i][j + 0] + bias[n0 + tx * 8 + j + 0];
                o.y = acc[i][j + 1] + bias[n0 + tx * 8 + j + 1];
                o.z = acc[i][j + 2] + bias[n0 + tx * 8 + j + 2];
                o.w = acc[i][j + 3] + bias[n0 + tx * 8 + j + 3];
                *reinterpret_cast<float4*>(crow + j) = o;
            }
        }
    } else {
        // f0..f0+7 stays within one (which, head) since 8-aligned chunks of 32-wide heads
        const int f0 = n0 + tx * 8;
        const int which = f0 >> 8;           // 0=Q 1=K 2=V
        const int h = (f0 >> 5) & 7;
        const int d0 = f0 & 31;
        float* dst = (which == 0) ? g_Q : (which == 1) ? g_K : g_V;
        const float sc = (which == 0) ? 0.17677669529663689f : 1.0f;  // 1/sqrt(32)
#pragma unroll
        for (int i = 0; i < 8; i++) {
            const int row = m0 + ty * 8 + i;      // row = b*S + s
            const int b = row >> 12;
            const int s = row & (S_LEN - 1);
            float* drow = dst + (((size_t)(b * NH + h) * S_LEN + s) * HD) + d0;
#pragma unroll
            for (int j = 0; j < 8; j++)
                drow[j] = (acc[i][j] + bias[f0 + j]) * sc;
        }
    }
}

// ================= banded attention: 1 thread = 1 query, online softmax =================
// Block: 128 queries of one (b,h). Keys needed: [q0-64, q0+127+64] -> 256 rows.
// smem: K tile + V tile, 256 x 32 padded to 33 (bank = (j+d) mod 32, consecutive-j lanes -> conflict-free)
#define TQ 128
#define KROWS 256
#define KPAD 33
#define ATTN_SMEM (2 * KROWS * KPAD * (int)sizeof(float))

__global__ __launch_bounds__(TQ) void attn_kernel()
{
    extern __shared__ float smem[];
    float* Ks = smem;
    float* Vs = smem + KROWS * KPAD;

    const int qt = blockIdx.x;
    const int h = blockIdx.y;
    const int b = blockIdx.z;
    const int q0 = qt * TQ;
    const int jbase = q0 - WIN;
    const size_t base = (size_t)(b * NH + h) * S_LEN * HD;
    const int t = threadIdx.x;

    // cooperative K/V tile load (coalesced: 4 consecutive rows per step)
    for (int idx = t; idx < KROWS * HD; idx += TQ) {
        const int r = idx >> 5;
        const int d = idx & 31;
        const int j = jbase + r;
        const bool ok = (j >= 0) && (j < S_LEN);
        const size_t g = base + (size_t)(ok ? j : 0) * HD + d;
        Ks[r * KPAD + d] = ok ? g_K[g] : 0.f;
        Vs[r * KPAD + d] = ok ? g_V[g] : 0.f;
    }
    __syncthreads();

    const int q = q0 + t;
    float qreg[32];
#pragma unroll
    for (int d = 0; d < 32; d++) qreg[d] = g_Q[base + (size_t)q * HD + d];  // pre-scaled

    float m = -1e30f, l = 0.f;
    float acc[32];
#pragma unroll
    for (int d = 0; d < 32; d++) acc[d] = 0.f;

    const int lo = (q - WIN > 0) ? q - WIN : 0;
    const int hi = (q + WIN < S_LEN - 1) ? q + WIN : S_LEN - 1;
    const float LOG2E = 1.44269504088896340736f;

    for (int j = lo; j <= hi; j++) {
        const int r = j - jbase;
        const float* kr = &Ks[r * KPAD];
        float s = 0.f;
#pragma unroll
        for (int d = 0; d < 32; d++) s = fmaf(qreg[d], kr[d], s);
        const float mn = fmaxf(m, s);
        const float corr = exp2f((m - mn) * LOG2E);
        const float p = exp2f((s - mn) * LOG2E);
        l = l * corr + p;
        const float* vr = &Vs[r * KPAD];
#pragma unroll
        for (int d = 0; d < 32; d++) acc[d] = fmaf(acc[d], corr, p * vr[d]);
        m = mn;
    }

    const float inv = 1.f / l;
    float* op = g_O + ((size_t)(b * S_LEN + q)) * EDIM + h * HD;
#pragma unroll
    for (int d = 0; d < 32; d += 4) {
        float4 o;
        o.x = acc[d + 0] * inv;
        o.y = acc[d + 1] * inv;
        o.z = acc[d + 2] * inv;
        o.w = acc[d + 3] * inv;
        *reinterpret_cast<float4*>(op + d) = o;
    }
}

// ================= launch =================
extern "C" void kernel_launch(void* const* d_in, const int* in_sizes, int n_in,
                              void* d_out, int out_size)
{
    const float* x    = (const float*)d_in[0];   // [2,4096,256]
    const float* in_w = (const float*)d_in[1];   // [768,256]
    const float* in_b = (const float*)d_in[2];   // [768]
    const float* ow   = (const float*)d_in[3];   // [256,256]
    const float* ob   = (const float*)d_in[4];   // [256]
    float* out = (float*)d_out;                  // [2,4096,256]

    const int M = BATCH * S_LEN;                 // 8192

    // 1) QKV projection + scatter into g_Q/g_K/g_V
    {
        dim3 grid(768 / BN, M / BM);             // (6, 64)
        gemm_nt<1><<<grid, 256>>>(x, in_w, in_b, nullptr, M, 768, EDIM);
    }

    // 2) banded attention -> g_O [B,S,E]
    {
        static bool attr_done = false;
        (void)attr_done;
        cudaFuncSetAttribute(attn_kernel, cudaFuncAttributeMaxDynamicSharedMemorySize, ATTN_SMEM);
        dim3 grid(S_LEN / TQ, NH, BATCH);        // (32, 8, 2)
        attn_kernel<<<grid, TQ, ATTN_SMEM>>>();
    }

    // 3) output projection g_O @ out_w^T + out_b -> out
    {
        float* Optr = nullptr;
        cudaGetSymbolAddress((void**)&Optr, g_O);
        dim3 grid(EDIM / BN, M / BM);            // (2, 64)
        gemm_nt<0><<<grid, 256>>>(Optr, ow, ob, out, M, EDIM, EDIM);
    }
}

// round 3
// speedup vs baseline: 1.2735x; 1.2735x over previous
#include <cuda_runtime.h>
#include <cuda_bf16.h>
#include <math.h>
#include <stdint.h>

#define S_LEN  4096
#define BATCH  2
#define NH     8
#define HD     32
#define EDIM   256
#define WIN    64

#define KTOT   768        // augmented K: [hi|hi|lo] vs [hi|lo|hi]
#define CH     64         // bf16 per K-chunk (128 bytes per row)
#define NCHUNK (KTOT / CH)
#define TM     128
#define TN     128

// ---- scratch (__device__ globals; no allocation allowed) ----
__device__ float g_Q[BATCH * NH * S_LEN * HD];           // pre-scaled by 1/sqrt(32)
__device__ float g_K[BATCH * NH * S_LEN * HD];
__device__ float g_V[BATCH * NH * S_LEN * HD];
__device__ __nv_bfloat16 g_Xs  [BATCH * S_LEN * KTOT];   // x        -> [hi, hi, lo]
__device__ __nv_bfloat16 g_Os  [BATCH * S_LEN * KTOT];   // attn out -> [hi, hi, lo]
__device__ __nv_bfloat16 g_Win2 [3 * EDIM * KTOT];       // in_proj_w -> [hi, lo, hi]
__device__ __nv_bfloat16 g_Wout2[EDIM * KTOT];           // out_w     -> [hi, lo, hi]

// ============================ helpers ============================
__device__ __forceinline__ uint32_t smem_u32(const void* p) {
    uint32_t a;
    asm("{ .reg .u64 t; cvta.to.shared.u64 t, %1; cvt.u32.u64 %0, t; }" : "=r"(a) : "l"(p));
    return a;
}
__device__ __forceinline__ uint32_t sw128(uint32_t off) {
    return off ^ ((off >> 3) & 0x70);
}
__device__ __forceinline__ void ldmx4(uint32_t& r0, uint32_t& r1, uint32_t& r2, uint32_t& r3,
                                      uint32_t addr) {
    asm volatile("ldmatrix.sync.aligned.m8n8.x4.shared.b16 {%0,%1,%2,%3}, [%4];"
                 : "=r"(r0), "=r"(r1), "=r"(r2), "=r"(r3) : "r"(addr));
}
__device__ __forceinline__ void ldmx2(uint32_t& r0, uint32_t& r1, uint32_t addr) {
    asm volatile("ldmatrix.sync.aligned.m8n8.x2.shared.b16 {%0,%1}, [%2];"
                 : "=r"(r0), "=r"(r1) : "r"(addr));
}
__device__ __forceinline__ void mma16816(float* c, const uint32_t* a, const uint32_t* b) {
    asm volatile(
        "mma.sync.aligned.m16n8k16.row.col.f32.bf16.bf16.f32 "
        "{%0,%1,%2,%3}, {%4,%5,%6,%7}, {%8,%9}, {%0,%1,%2,%3};"
        : "+f"(c[0]), "+f"(c[1]), "+f"(c[2]), "+f"(c[3])
        : "r"(a[0]), "r"(a[1]), "r"(a[2]), "r"(a[3]), "r"(b[0]), "r"(b[1]));
}

// ============================ conversion kernels ============================
__global__ __launch_bounds__(256) void conv_x(const float* __restrict__ x) {
    int idx = blockIdx.x * 256 + threadIdx.x;          // over 8192*256
    float v = x[idx];
    int row = idx >> 8, c = idx & 255;
    __nv_bfloat16 hi = __float2bfloat16(v);
    __nv_bfloat16 lo = __float2bfloat16(v - __bfloat162float(hi));
    __nv_bfloat16* o = g_Xs + (size_t)row * KTOT;
    o[c] = hi; o[256 + c] = hi; o[512 + c] = lo;       // [hi, hi, lo]
}
__global__ __launch_bounds__(256) void conv_w(const float* __restrict__ w,
                                              __nv_bfloat16* __restrict__ o2, int n) {
    int idx = blockIdx.x * 256 + threadIdx.x;
    if (idx >= n) return;
    float v = w[idx];
    int row = idx >> 8, c = idx & 255;
    __nv_bfloat16 hi = __float2bfloat16(v);
    __nv_bfloat16 lo = __float2bfloat16(v - __bfloat162float(hi));
    __nv_bfloat16* o = o2 + (size_t)row * KTOT;
    o[c] = hi; o[256 + c] = lo; o[512 + c] = hi;       // [hi, lo, hi]
}

// ============================ HMMA GEMM (mma.sync bf16) ============================
// C[M,N] = A''[M,768] @ B''[N,768]^T + bias.  128x128 tile, 8 warps (2x4),
// per-warp 64x32 via m16n8k16.  MODE 1: scatter to g_Q/g_K/g_V; MODE 0: plain C.
template <int MODE>
__global__ __launch_bounds__(256) void hgemm(
    const __nv_bfloat16* __restrict__ A, const __nv_bfloat16* __restrict__ B,
    const float* __restrict__ bias, float* __restrict__ C)
{
    // union: mainloop A(16KB)+B(16KB)  |  epilogue stage 64x132 fp32 (33.8KB)
    __shared__ __align__(16) unsigned char sm[16384 + 16384 + 1536];
    __shared__ float sbias[TN];
    unsigned char* smA = sm;
    unsigned char* smB = sm + 16384;
    const uint32_t sA = smem_u32(smA), sB = smem_u32(smB);

    const int tid = threadIdx.x, lane = tid & 31, wid = tid >> 5;
    const int warp_m = wid >> 2;          // 0..1  (64 rows)
    const int warp_n = wid & 3;           // 0..3  (32 cols)
    const int m0 = blockIdx.y * TM, n0 = blockIdx.x * TN;

    if (tid < TN) sbias[tid] = bias[n0 + tid];

    float acc[4][4][4];
#pragma unroll
    for (int i = 0; i < 4; i++)
#pragma unroll
        for (int j = 0; j < 4; j++)
#pragma unroll
            for (int e = 0; e < 4; e++) acc[i][j][e] = 0.f;

    // ldmatrix per-lane address components (within-chunk)
    const int arow = warp_m * 64 + (lane & 15);
    const int akb  = (lane >> 4) * 16;
    const int brow = warp_n * 32 + (lane & 7);
    const int bkb  = ((lane >> 3) & 1) * 16;

    for (int ch = 0; ch < NCHUNK; ch++) {
        // gmem loads (8 x uint4 per thread)
        const char* gA = (const char*)(A + (size_t)m0 * KTOT + ch * CH);
        const char* gB = (const char*)(B + (size_t)n0 * KTOT + ch * CH);
        uint4 va[4], vb[4];
#pragma unroll
        for (int i = 0; i < 4; i++) {
            int cid = tid + 256 * i;              // 0..1023: 128 rows x 8 16B-chunks
            int r = cid >> 3, c16 = cid & 7;
            va[i] = *reinterpret_cast<const uint4*>(gA + (size_t)r * (KTOT * 2) + c16 * 16);
            vb[i] = *reinterpret_cast<const uint4*>(gB + (size_t)r * (KTOT * 2) + c16 * 16);
        }
        __syncthreads();   // previous chunk compute done
#pragma unroll
        for (int i = 0; i < 4; i++) {
            int cid = tid + 256 * i;
            int r = cid >> 3, c16 = cid & 7;
            uint32_t sw = sw128(r * 128 + c16 * 16);
            *reinterpret_cast<uint4*>(smA + sw) = va[i];
            *reinterpret_cast<uint4*>(smB + sw) = vb[i];
        }
        __syncthreads();

#pragma unroll
        for (int k16 = 0; k16 < 4; k16++) {
            uint32_t a[4][4], b[4][2];
#pragma unroll
            for (int mt = 0; mt < 4; mt++) {
                uint32_t addr = sA + sw128((arow + mt * 16) * 128 + k16 * 32 + akb);
                ldmx4(a[mt][0], a[mt][1], a[mt][2], a[mt][3], addr);
            }
#pragma unroll
            for (int nt = 0; nt < 4; nt++) {
                uint32_t addr = sB + sw128((brow + nt * 8) * 128 + k16 * 32 + bkb);
                ldmx2(b[nt][0], b[nt][1], addr);
            }
#pragma unroll
            for (int mt = 0; mt < 4; mt++)
#pragma unroll
                for (int nt = 0; nt < 4; nt++)
                    mma16816(acc[mt][nt], a[mt], b[nt]);
        }
    }

    // ================= epilogue: stage 64-row halves through smem =================
    float* stage = reinterpret_cast<float*>(sm);   // 64 x 132
    const int b_idx = m0 >> 12, s0 = m0 & (S_LEN - 1);
    const int which = n0 >> 8;                     // tiles never straddle Q/K/V
    const float sc = (MODE == 1 && which == 0) ? 0.17677669529663689f : 1.0f;

#pragma unroll
    for (int half = 0; half < 2; half++) {
        __syncthreads();
        if (warp_m == half) {
#pragma unroll
            for (int mt = 0; mt < 4; mt++) {
                int r0 = mt * 16 + (lane >> 2);
#pragma unroll
                for (int nt = 0; nt < 4; nt++) {
                    int cc = warp_n * 32 + nt * 8 + (lane & 3) * 2;
                    *reinterpret_cast<float2*>(&stage[r0 * 132 + cc]) =
                        make_float2(acc[mt][nt][0], acc[mt][nt][1]);
                    *reinterpret_cast<float2*>(&stage[(r0 + 8) * 132 + cc]) =
                        make_float2(acc[mt][nt][2], acc[mt][nt][3]);
                }
            }
        }
        __syncthreads();
        // coalesced copy out: 64 x 128 floats = 2048 float4
#pragma unroll
        for (int i = 0; i < 8; i++) {
            int e = tid + 256 * i;                 // 0..2047
            int r = e >> 5, c4 = e & 31;           // row 0..63, float4 col 0..31
            float4 v;
            v.x = (stage[r * 132 + c4 * 4 + 0] + sbias[c4 * 4 + 0]) * sc;
            v.y = (stage[r * 132 + c4 * 4 + 1] + sbias[c4 * 4 + 1]) * sc;
            v.z = (stage[r * 132 + c4 * 4 + 2] + sbias[c4 * 4 + 2]) * sc;
            v.w = (stage[r * 132 + c4 * 4 + 3] + sbias[c4 * 4 + 3]) * sc;
            int grow = m0 + half * 64 + r;
            if (MODE == 1) {
                int f = n0 + c4 * 4;               // global feature
                int h = (f >> 5) & 7, d0 = f & 31;
                float* dst = (which == 0) ? g_Q : (which == 1) ? g_K : g_V;
                int s = grow & (S_LEN - 1);
                *reinterpret_cast<float4*>(
                    dst + ((size_t)(b_idx * NH + h) * S_LEN + s) * HD + d0) = v;
            } else {
                *reinterpret_cast<float4*>(C + (size_t)grow * EDIM + n0 + c4 * 4) = v;
            }
        }
    }
}

// ============================ banded attention ============================
// 1 thread = 1 query, 128 queries/block; K/V tiles in smem; online softmax.
// Epilogue writes bf16 [hi, hi, lo] augmented rows of g_Os for the out-proj GEMM.
#define TQ    128
#define KROWS 256
#define KPAD  33
#define ATTN_SMEM (2 * KROWS * KPAD * (int)sizeof(float))

__global__ __launch_bounds__(TQ) void attn_kernel()
{
    extern __shared__ float smem[];
    float* Ks = smem;
    float* Vs = smem + KROWS * KPAD;

    const int qt = blockIdx.x;
    const int h  = blockIdx.y;
    const int b  = blockIdx.z;
    const int q0 = qt * TQ;
    const int jbase = q0 - WIN;
    const size_t base = (size_t)(b * NH + h) * S_LEN * HD;
    const int t = threadIdx.x;

    for (int idx = t; idx < KROWS * HD; idx += TQ) {
        const int r = idx >> 5;
        const int d = idx & 31;
        const int j = jbase + r;
        const bool ok = (j >= 0) && (j < S_LEN);
        const size_t g = base + (size_t)(ok ? j : 0) * HD + d;
        Ks[r * KPAD + d] = ok ? g_K[g] : 0.f;
        Vs[r * KPAD + d] = ok ? g_V[g] : 0.f;
    }
    __syncthreads();

    const int q = q0 + t;
    float qreg[32];
#pragma unroll
    for (int d = 0; d < 32; d++) qreg[d] = g_Q[base + (size_t)q * HD + d];

    float m = -1e30f, l = 0.f;
    float acc[32];
#pragma unroll
    for (int d = 0; d < 32; d++) acc[d] = 0.f;

    const int lo = (q - WIN > 0) ? q - WIN : 0;
    const int hi = (q + WIN < S_LEN - 1) ? q + WIN : S_LEN - 1;
    const float LOG2E = 1.44269504088896340736f;

    for (int j = lo; j <= hi; j++) {
        const int r = j - jbase;
        const float* kr = &Ks[r * KPAD];
        float s = 0.f;
#pragma unroll
        for (int d = 0; d < 32; d++) s = fmaf(qreg[d], kr[d], s);
        const float mn = fmaxf(m, s);
        const float corr = exp2f((m - mn) * LOG2E);
        const float p = exp2f((s - mn) * LOG2E);
        l = l * corr + p;
        const float* vr = &Vs[r * KPAD];
#pragma unroll
        for (int d = 0; d < 32; d++) acc[d] = fmaf(acc[d], corr, p * vr[d]);
        m = mn;
    }

    const float inv = 1.f / l;

    // stage fp32 result, then coalesced bf16 [hi, hi, lo] writes into g_Os
    __syncthreads();                 // done reading Ks/Vs
    float* stg = smem;               // 128 x 33
#pragma unroll
    for (int d = 0; d < 32; d++) stg[t * 33 + d] = acc[d] * inv;
    __syncthreads();

    const int m_base = b * S_LEN + q0;
#pragma unroll
    for (int i = 0; i < 4; i++) {
        int e = t + TQ * i;          // 0..511
        int r = e >> 2, c8 = e & 3;  // row 0..127, 8-bf16 chunk 0..3
        union { __nv_bfloat16 v[8]; uint4 u; } H, L;
#pragma unroll
        for (int j = 0; j < 8; j++) {
            float v = stg[r * 33 + c8 * 8 + j];
            __nv_bfloat16 hv = __float2bfloat16(v);
            H.v[j] = hv;
            L.v[j] = __float2bfloat16(v - __bfloat162float(hv));
        }
        __nv_bfloat16* orow = g_Os + (size_t)(m_base + r) * KTOT + h * HD + c8 * 8;
        *reinterpret_cast<uint4*>(orow)       = H.u;
        *reinterpret_cast<uint4*>(orow + 256) = H.u;
        *reinterpret_cast<uint4*>(orow + 512) = L.u;
    }
}

// ============================ launch ============================
extern "C" void kernel_launch(void* const* d_in, const int* in_sizes, int n_in,
                              void* d_out, int out_size)
{
    const float* x    = (const float*)d_in[0];   // [2,4096,256]
    const float* in_w = (const float*)d_in[1];   // [768,256]
    const float* in_b = (const float*)d_in[2];   // [768]
    const float* ow   = (const float*)d_in[3];   // [256,256]
    const float* ob   = (const float*)d_in[4];   // [256]
    float* out = (float*)d_out;                  // [2,4096,256]

    __nv_bfloat16 *Xs, *Os, *Win2, *Wout2;
    cudaGetSymbolAddress((void**)&Xs,    g_Xs);
    cudaGetSymbolAddress((void**)&Os,    g_Os);
    cudaGetSymbolAddress((void**)&Win2,  g_Win2);
    cudaGetSymbolAddress((void**)&Wout2, g_Wout2);

    // 0) split-bf16 conversions
    conv_x<<<(BATCH * S_LEN * EDIM) / 256, 256>>>(x);
    conv_w<<<(3 * EDIM * EDIM + 255) / 256, 256>>>(in_w, Win2, 3 * EDIM * EDIM);
    conv_w<<<(EDIM * EDIM + 255) / 256, 256>>>(ow, Wout2, EDIM * EDIM);

    // 1) QKV projection (HMMA) -> g_Q/g_K/g_V
    {
        dim3 grid(3 * EDIM / TN, BATCH * S_LEN / TM);   // (6, 64)
        hgemm<1><<<grid, 256>>>(Xs, Win2, in_b, nullptr);
    }

    // 2) banded attention -> g_Os (bf16 augmented)
    {
        cudaFuncSetAttribute(attn_kernel, cudaFuncAttributeMaxDynamicSharedMemorySize, ATTN_SMEM);
        dim3 grid(S_LEN / TQ, NH, BATCH);               // (32, 8, 2)
        attn_kernel<<<grid, TQ, ATTN_SMEM>>>();
    }

    // 3) output projection (HMMA) -> out
    {
        dim3 grid(EDIM / TN, BATCH * S_LEN / TM);       // (2, 64)
        hgemm<0><<<grid, 256>>>(Os, Wout2, ob, out);
    }
}

// round 4
// speedup vs baseline: 2.6612x; 2.0897x over previous
#include <cuda_runtime.h>
#include <cuda_bf16.h>
#include <math.h>
#include <stdint.h>

#define S_LEN  4096
#define BATCH  2
#define NH     8
#define HD     32
#define EDIM   256
#define WIN    64

#define KTOT   768        // augmented K: [hi|hi|lo] vs [hi|lo|hi]
#define CH     64         // bf16 per K-chunk (128 bytes per row)
#define NCHUNK (KTOT / CH)
#define TM     128
#define TN     128

typedef unsigned long long ull;

// ---- scratch (__device__ globals; no allocation allowed) ----
__device__ float g_Q[BATCH * NH * S_LEN * HD];           // pre-scaled by LOG2E/sqrt(32)
__device__ float g_K[BATCH * NH * S_LEN * HD];
__device__ float g_V[BATCH * NH * S_LEN * HD];
__device__ __nv_bfloat16 g_Xs  [BATCH * S_LEN * KTOT];   // x        -> [hi, hi, lo]
__device__ __nv_bfloat16 g_Os  [BATCH * S_LEN * KTOT];   // attn out -> [hi, hi, lo]
__device__ __nv_bfloat16 g_Win2 [3 * EDIM * KTOT];       // in_proj_w -> [hi, lo, hi]
__device__ __nv_bfloat16 g_Wout2[EDIM * KTOT];           // out_w     -> [hi, lo, hi]

// ============================ helpers ============================
__device__ __forceinline__ uint32_t smem_u32(const void* p) {
    uint32_t a;
    asm("{ .reg .u64 t; cvta.to.shared.u64 t, %1; cvt.u32.u64 %0, t; }" : "=r"(a) : "l"(p));
    return a;
}
__device__ __forceinline__ uint32_t sw128(uint32_t off) {
    return off ^ ((off >> 3) & 0x70);
}
__device__ __forceinline__ void ldmx4(uint32_t& r0, uint32_t& r1, uint32_t& r2, uint32_t& r3,
                                      uint32_t addr) {
    asm volatile("ldmatrix.sync.aligned.m8n8.x4.shared.b16 {%0,%1,%2,%3}, [%4];"
                 : "=r"(r0), "=r"(r1), "=r"(r2), "=r"(r3) : "r"(addr));
}
__device__ __forceinline__ void ldmx2(uint32_t& r0, uint32_t& r1, uint32_t addr) {
    asm volatile("ldmatrix.sync.aligned.m8n8.x2.shared.b16 {%0,%1}, [%2];"
                 : "=r"(r0), "=r"(r1) : "r"(addr));
}
__device__ __forceinline__ void mma16816(float* c, const uint32_t* a, const uint32_t* b) {
    asm volatile(
        "mma.sync.aligned.m16n8k16.row.col.f32.bf16.bf16.f32 "
        "{%0,%1,%2,%3}, {%4,%5,%6,%7}, {%8,%9}, {%0,%1,%2,%3};"
        : "+f"(c[0]), "+f"(c[1]), "+f"(c[2]), "+f"(c[3])
        : "r"(a[0]), "r"(a[1]), "r"(a[2]), "r"(a[3]), "r"(b[0]), "r"(b[1]));
}
// packed f32x2 (sm_100+ family PTX, not arch-'a' gated)
__device__ __forceinline__ ull fma2(ull a, ull b, ull c) {
    ull d; asm("fma.rn.f32x2 %0, %1, %2, %3;" : "=l"(d) : "l"(a), "l"(b), "l"(c)); return d;
}
__device__ __forceinline__ ull add2(ull a, ull b) {
    ull d; asm("add.rn.f32x2 %0, %1, %2;" : "=l"(d) : "l"(a), "l"(b)); return d;
}
__device__ __forceinline__ ull pack2(float x, float y) {
    ull r; asm("mov.b64 %0, {%1, %2};" : "=l"(r) : "f"(x), "f"(y)); return r;
}
__device__ __forceinline__ float2 unpack2(ull a) {
    float x, y; asm("mov.b64 {%0, %1}, %2;" : "=f"(x), "=f"(y) : "l"(a));
    return make_float2(x, y);
}

// ============================ conversion kernels ============================
__global__ __launch_bounds__(256) void conv_x(const float* __restrict__ x) {
    int idx = blockIdx.x * 256 + threadIdx.x;          // over 8192*256
    float v = x[idx];
    int row = idx >> 8, c = idx & 255;
    __nv_bfloat16 hi = __float2bfloat16(v);
    __nv_bfloat16 lo = __float2bfloat16(v - __bfloat162float(hi));
    __nv_bfloat16* o = g_Xs + (size_t)row * KTOT;
    o[c] = hi; o[256 + c] = hi; o[512 + c] = lo;       // [hi, hi, lo]
}
__global__ __launch_bounds__(256) void conv_w(const float* __restrict__ w,
                                              __nv_bfloat16* __restrict__ o2, int n) {
    int idx = blockIdx.x * 256 + threadIdx.x;
    if (idx >= n) return;
    float v = w[idx];
    int row = idx >> 8, c = idx & 255;
    __nv_bfloat16 hi = __float2bfloat16(v);
    __nv_bfloat16 lo = __float2bfloat16(v - __bfloat162float(hi));
    __nv_bfloat16* o = o2 + (size_t)row * KTOT;
    o[c] = hi; o[256 + c] = lo; o[512 + c] = hi;       // [hi, lo, hi]
}

// ============================ HMMA GEMM (cp.async double-buffered) ============================
// C[M,N] = A''[M,768] @ B''[N,768]^T + bias.  128x128 tile, 8 warps (2x4),
// per-warp 64x32 via m16n8k16.  MODE 1: scatter to g_Q/g_K/g_V; MODE 0: plain C.
// dynamic smem: 2 stages x (16KB A + 16KB B) = 64KB; epilogue stage aliases it.
#define GEMM_SMEM 65536

template <int MODE>
__global__ __launch_bounds__(256, 2) void hgemm(
    const __nv_bfloat16* __restrict__ A, const __nv_bfloat16* __restrict__ B,
    const float* __restrict__ bias, float* __restrict__ C)
{
    extern __shared__ __align__(16) unsigned char dsm[];
    __shared__ float sbias[TN];
    const uint32_t sbase = smem_u32(dsm);

    const int tid = threadIdx.x, lane = tid & 31, wid = tid >> 5;
    const int warp_m = wid >> 2;          // 0..1  (64 rows)
    const int warp_n = wid & 3;           // 0..3  (32 cols)
    const int m0 = blockIdx.y * TM, n0 = blockIdx.x * TN;

    if (tid < TN) sbias[tid] = bias[n0 + tid];

    float acc[4][4][4];
#pragma unroll
    for (int i = 0; i < 4; i++)
#pragma unroll
        for (int j = 0; j < 4; j++)
#pragma unroll
            for (int e = 0; e < 4; e++) acc[i][j][e] = 0.f;

    // per-thread cp.async source/dest components
    const int r_ld = tid >> 3, c16 = tid & 7;     // base row (stride 32), 16B col
    const char* gA0 = (const char*)(A + (size_t)m0 * KTOT) + (size_t)r_ld * (KTOT * 2) + c16 * 16;
    const char* gB0 = (const char*)(B + (size_t)n0 * KTOT) + (size_t)r_ld * (KTOT * 2) + c16 * 16;

    // ldmatrix per-lane address components (within-chunk)
    const int arow = warp_m * 64 + (lane & 15);
    const int akb  = (lane >> 4) * 16;
    const int brow = warp_n * 32 + (lane & 7);
    const int bkb  = ((lane >> 3) & 1) * 16;

#define ISSUE_CHUNK(ch, buf)                                                         \
    do {                                                                             \
        uint32_t dA = sbase + (buf) * 32768;                                         \
        uint32_t dB = dA + 16384;                                                    \
        const char* ga = gA0 + (ch) * 128;                                           \
        const char* gb = gB0 + (ch) * 128;                                           \
        _Pragma("unroll")                                                            \
        for (int i = 0; i < 4; i++) {                                                \
            uint32_t sw = sw128((r_ld + i * 32) * 128 + c16 * 16);                   \
            asm volatile("cp.async.cg.shared.global [%0], [%1], 16;"                 \
                         :: "r"(dA + sw), "l"(ga + (size_t)i * 32 * (KTOT * 2)));    \
            asm volatile("cp.async.cg.shared.global [%0], [%1], 16;"                 \
                         :: "r"(dB + sw), "l"(gb + (size_t)i * 32 * (KTOT * 2)));    \
        }                                                                            \
        asm volatile("cp.async.commit_group;" ::: "memory");                         \
    } while (0)

    ISSUE_CHUNK(0, 0);

    for (int ch = 0; ch < NCHUNK; ch++) {
        if (ch + 1 < NCHUNK) {
            ISSUE_CHUNK(ch + 1, (ch + 1) & 1);
            asm volatile("cp.async.wait_group 1;" ::: "memory");
        } else {
            asm volatile("cp.async.wait_group 0;" ::: "memory");
        }
        __syncthreads();

        const uint32_t sA = sbase + (ch & 1) * 32768;
        const uint32_t sB = sA + 16384;
#pragma unroll
        for (int k16 = 0; k16 < 4; k16++) {
            uint32_t a[4][4], b[4][2];
#pragma unroll
            for (int mt = 0; mt < 4; mt++) {
                uint32_t addr = sA + sw128((arow + mt * 16) * 128 + k16 * 32 + akb);
                ldmx4(a[mt][0], a[mt][1], a[mt][2], a[mt][3], addr);
            }
#pragma unroll
            for (int nt = 0; nt < 4; nt++) {
                uint32_t addr = sB + sw128((brow + nt * 8) * 128 + k16 * 32 + bkb);
                ldmx2(b[nt][0], b[nt][1], addr);
            }
#pragma unroll
            for (int mt = 0; mt < 4; mt++)
#pragma unroll
                for (int nt = 0; nt < 4; nt++)
                    mma16816(acc[mt][nt], a[mt], b[nt]);
        }
        __syncthreads();   // done reading this buffer before its next fill
    }
#undef ISSUE_CHUNK

    // ================= epilogue: stage 64-row halves through smem =================
    float* stage = reinterpret_cast<float*>(dsm);   // 64 x 132 fp32 (33.8KB, aliases bufs)
    const int b_idx = m0 >> 12;
    const int which = n0 >> 8;                      // tiles never straddle Q/K/V
    // Q pre-scale: LOG2E / sqrt(32)  (exp2-domain scores)
    const float sc = (MODE == 1 && which == 0) ? 0.2550348772f : 1.0f;

#pragma unroll
    for (int half = 0; half < 2; half++) {
        __syncthreads();
        if (warp_m == half) {
#pragma unroll
            for (int mt = 0; mt < 4; mt++) {
                int r0 = mt * 16 + (lane >> 2);
#pragma unroll
                for (int nt = 0; nt < 4; nt++) {
                    int cc = warp_n * 32 + nt * 8 + (lane & 3) * 2;
                    *reinterpret_cast<float2*>(&stage[r0 * 132 + cc]) =
                        make_float2(acc[mt][nt][0], acc[mt][nt][1]);
                    *reinterpret_cast<float2*>(&stage[(r0 + 8) * 132 + cc]) =
                        make_float2(acc[mt][nt][2], acc[mt][nt][3]);
                }
            }
        }
        __syncthreads();
#pragma unroll
        for (int i = 0; i < 8; i++) {
            int e = tid + 256 * i;                 // 0..2047
            int r = e >> 5, c4 = e & 31;           // row 0..63, float4 col 0..31
            float4 v;
            v.x = (stage[r * 132 + c4 * 4 + 0] + sbias[c4 * 4 + 0]) * sc;
            v.y = (stage[r * 132 + c4 * 4 + 1] + sbias[c4 * 4 + 1]) * sc;
            v.z = (stage[r * 132 + c4 * 4 + 2] + sbias[c4 * 4 + 2]) * sc;
            v.w = (stage[r * 132 + c4 * 4 + 3] + sbias[c4 * 4 + 3]) * sc;
            int grow = m0 + half * 64 + r;
            if (MODE == 1) {
                int f = n0 + c4 * 4;               // global feature
                int h = (f >> 5) & 7, d0 = f & 31;
                float* dst = (which == 0) ? g_Q : (which == 1) ? g_K : g_V;
                int s = grow & (S_LEN - 1);
                *reinterpret_cast<float4*>(
                    dst + ((size_t)(b_idx * NH + h) * S_LEN + s) * HD + d0) = v;
            } else {
                *reinterpret_cast<float4*>(C + (size_t)grow * EDIM + n0 + c4 * 4) = v;
            }
        }
    }
}

// ============================ banded attention ============================
// 256 queries/block, 8 warps. Each warp: 32 consecutive queries; all lanes walk
// the SAME key row (uniform LDS -> broadcast, 32x less smem traffic).
// No online max (scores provably small; exp2-domain, LOG2E folded into Q).
// Epilogue writes bf16 [hi, hi, lo] augmented rows of g_Os for the out-proj GEMM.
#define TQ    256
#define KROWS 384
#define ATTN_SMEM (2 * KROWS * HD * (int)sizeof(float))   // 96KB

__global__ __launch_bounds__(TQ) void attn_kernel()
{
    extern __shared__ __align__(16) float smem[];
    float* Ks = smem;                 // [384][32] fp32, row-major, no pad
    float* Vs = smem + KROWS * HD;

    const int qt = blockIdx.x;
    const int h  = blockIdx.y;
    const int b  = blockIdx.z;
    const int q0 = qt * TQ;
    const int jbase = q0 - WIN;
    const size_t base = (size_t)(b * NH + h) * S_LEN * HD;
    const int t = threadIdx.x, w = t >> 5;

    // cooperative K/V load: 384 rows x 8 float4 each
    for (int i = t; i < KROWS * 8; i += TQ) {
        const int r = i >> 3, c = i & 7;
        const int j = jbase + r;
        const bool ok = (j >= 0) && (j < S_LEN);
        float4 kv = make_float4(0.f, 0.f, 0.f, 0.f), vv = kv;
        if (ok) {
            kv = reinterpret_cast<const float4*>(g_K + base + (size_t)j * HD)[c];
            vv = reinterpret_cast<const float4*>(g_V + base + (size_t)j * HD)[c];
        }
        reinterpret_cast<float4*>(Ks + r * HD)[c] = kv;
        reinterpret_cast<float4*>(Vs + r * HD)[c] = vv;
    }
    __syncthreads();

    const int q = q0 + t;
    ull q2[16];
    {
        const ulonglong2* qrow = reinterpret_cast<const ulonglong2*>(g_Q + base + (size_t)q * HD);
#pragma unroll
        for (int i = 0; i < 8; i++) { ulonglong2 u = qrow[i]; q2[2 * i] = u.x; q2[2 * i + 1] = u.y; }
    }

    ull acc2[16];
#pragma unroll
    for (int i = 0; i < 16; i++) acc2[i] = 0ull;
    float l = 0.f;

    const int jlo = (q - WIN > 0) ? q - WIN : 0;
    const int jhi = (q + WIN < S_LEN - 1) ? q + WIN : S_LEN - 1;
    const int rb = w * 32;            // warp's first row

    for (int rr = 0; rr < 160; rr++) {
        const int r = rb + rr;
        const int j = jbase + r;
        const ulonglong2* kr = reinterpret_cast<const ulonglong2*>(Ks + r * HD);
        ull c0 = 0ull, c1 = 0ull;
#pragma unroll
        for (int i = 0; i < 8; i++) {
            ulonglong2 k = kr[i];                       // uniform-address broadcast
            c0 = fma2(q2[2 * i], k.x, c0);
            c1 = fma2(q2[2 * i + 1], k.y, c1);
        }
        float2 sv = unpack2(add2(c0, c1));
        float s = sv.x + sv.y;
        s = (j >= jlo && j <= jhi) ? s : -1e30f;        // band + bounds mask
        const float p = exp2f(s);                       // scores already in log2 domain
        l += p;
        const ull p2 = pack2(p, p);
        const ulonglong2* vr = reinterpret_cast<const ulonglong2*>(Vs + r * HD);
#pragma unroll
        for (int i = 0; i < 8; i++) {
            ulonglong2 v = vr[i];                       // uniform-address broadcast
            acc2[2 * i]     = fma2(p2, v.x, acc2[2 * i]);
            acc2[2 * i + 1] = fma2(p2, v.y, acc2[2 * i + 1]);
        }
    }

    const float inv = 1.f / l;

    // stage fp32 result, then coalesced bf16 [hi, hi, lo] writes into g_Os
    __syncthreads();                  // done reading Ks/Vs
    float* stg = smem;                // 256 x 33
#pragma unroll
    for (int i = 0; i < 16; i++) {
        float2 a = unpack2(acc2[i]);
        stg[t * 33 + 2 * i]     = a.x * inv;
        stg[t * 33 + 2 * i + 1] = a.y * inv;
    }
    __syncthreads();

    const int m_base = b * S_LEN + q0;
#pragma unroll
    for (int i = 0; i < 4; i++) {
        int e = t + TQ * i;           // 0..1023
        int r = e >> 2, c8 = e & 3;   // row 0..255, 8-bf16 chunk 0..3
        union { __nv_bfloat16 v[8]; uint4 u; } H, L;
#pragma unroll
        for (int jj = 0; jj < 8; jj++) {
            float v = stg[r * 33 + c8 * 8 + jj];
            __nv_bfloat16 hv = __float2bfloat16(v);
            H.v[jj] = hv;
            L.v[jj] = __float2bfloat16(v - __bfloat162float(hv));
        }
        __nv_bfloat16* orow = g_Os + (size_t)(m_base + r) * KTOT + h * HD + c8 * 8;
        *reinterpret_cast<uint4*>(orow)       = H.u;
        *reinterpret_cast<uint4*>(orow + 256) = H.u;
        *reinterpret_cast<uint4*>(orow + 512) = L.u;
    }
}

// ============================ launch ============================
extern "C" void kernel_launch(void* const* d_in, const int* in_sizes, int n_in,
                              void* d_out, int out_size)
{
    const float* x    = (const float*)d_in[0];   // [2,4096,256]
    const float* in_w = (const float*)d_in[1];   // [768,256]
    const float* in_b = (const float*)d_in[2];   // [768]
    const float* ow   = (const float*)d_in[3];   // [256,256]
    const float* ob   = (const float*)d_in[4];   // [256]
    float* out = (float*)d_out;                  // [2,4096,256]

    __nv_bfloat16 *Xs, *Os, *Win2, *Wout2;
    cudaGetSymbolAddress((void**)&Xs,    g_Xs);
    cudaGetSymbolAddress((void**)&Os,    g_Os);
    cudaGetSymbolAddress((void**)&Win2,  g_Win2);
    cudaGetSymbolAddress((void**)&Wout2, g_Wout2);

    cudaFuncSetAttribute(hgemm<1>, cudaFuncAttributeMaxDynamicSharedMemorySize, GEMM_SMEM);
    cudaFuncSetAttribute(hgemm<0>, cudaFuncAttributeMaxDynamicSharedMemorySize, GEMM_SMEM);
    cudaFuncSetAttribute(attn_kernel, cudaFuncAttributeMaxDynamicSharedMemorySize, ATTN_SMEM);

    // 0) split-bf16 conversions
    conv_x<<<(BATCH * S_LEN * EDIM) / 256, 256>>>(x);
    conv_w<<<(3 * EDIM * EDIM + 255) / 256, 256>>>(in_w, Win2, 3 * EDIM * EDIM);
    conv_w<<<(EDIM * EDIM + 255) / 256, 256>>>(ow, Wout2, EDIM * EDIM);

    // 1) QKV projection (HMMA, pipelined) -> g_Q/g_K/g_V
    {
        dim3 grid(3 * EDIM / TN, BATCH * S_LEN / TM);   // (6, 64)
        hgemm<1><<<grid, 256, GEMM_SMEM>>>(Xs, Win2, in_b, nullptr);
    }

    // 2) banded attention -> g_Os (bf16 augmented)
    {
        dim3 grid(S_LEN / TQ, NH, BATCH);               // (16, 8, 2)
        attn_kernel<<<grid, TQ, ATTN_SMEM>>>();
    }

    // 3) output projection (HMMA, pipelined) -> out
    {
        dim3 grid(EDIM / TN, BATCH * S_LEN / TM);       // (2, 64)
        hgemm<0><<<grid, 256, GEMM_SMEM>>>(Os, Wout2, ob, out);
    }
}

// round 5
// speedup vs baseline: 3.6576x; 1.3744x over previous
#include <cuda_runtime.h>
#include <cuda_bf16.h>
#include <math.h>
#include <stdint.h>

#define S_LEN  4096
#define BATCH  2
#define NH     8
#define HD     32
#define EDIM   256
#define WIN    64

#define KTOT   768        // augmented K for projections: [hi|hi|lo] vs [hi|lo|hi]
#define CH     64
#define NCHUNK (KTOT / CH)
#define TM     128
#define TN     128

typedef unsigned long long ull;

// ---- scratch (__device__ globals; no allocation allowed) ----
__device__ __nv_bfloat16 g_Qb[BATCH * NH * S_LEN * 64];  // [hi(32)|lo(32)], scaled LOG2E/sqrt(32)
__device__ __nv_bfloat16 g_Kb[BATCH * NH * S_LEN * 64];  // [hi|lo]
__device__ __nv_bfloat16 g_Vb[BATCH * NH * S_LEN * 64];  // [hi|lo]
__device__ __nv_bfloat16 g_Xs  [BATCH * S_LEN * KTOT];   // x        -> [hi, hi, lo]
__device__ __nv_bfloat16 g_Os  [BATCH * S_LEN * KTOT];   // attn out -> [hi, hi, lo]
__device__ __nv_bfloat16 g_Win2 [3 * EDIM * KTOT];       // in_proj_w -> [hi, lo, hi]
__device__ __nv_bfloat16 g_Wout2[EDIM * KTOT];           // out_w     -> [hi, lo, hi]

// ============================ helpers ============================
__device__ __forceinline__ uint32_t smem_u32(const void* p) {
    uint32_t a;
    asm("{ .reg .u64 t; cvta.to.shared.u64 t, %1; cvt.u32.u64 %0, t; }" : "=r"(a) : "l"(p));
    return a;
}
__device__ __forceinline__ uint32_t sw128(uint32_t off) {
    return off ^ ((off >> 3) & 0x70);
}
__device__ __forceinline__ void ldmx4(uint32_t& r0, uint32_t& r1, uint32_t& r2, uint32_t& r3,
                                      uint32_t addr) {
    asm volatile("ldmatrix.sync.aligned.m8n8.x4.shared.b16 {%0,%1,%2,%3}, [%4];"
                 : "=r"(r0), "=r"(r1), "=r"(r2), "=r"(r3) : "r"(addr));
}
__device__ __forceinline__ void ldmx2(uint32_t& r0, uint32_t& r1, uint32_t addr) {
    asm volatile("ldmatrix.sync.aligned.m8n8.x2.shared.b16 {%0,%1}, [%2];"
                 : "=r"(r0), "=r"(r1) : "r"(addr));
}
__device__ __forceinline__ void ldmx2t(uint32_t& r0, uint32_t& r1, uint32_t addr) {
    asm volatile("ldmatrix.sync.aligned.m8n8.x2.trans.shared.b16 {%0,%1}, [%2];"
                 : "=r"(r0), "=r"(r1) : "r"(addr));
}
__device__ __forceinline__ void mma16816(float* c, const uint32_t* a, const uint32_t* b) {
    asm volatile(
        "mma.sync.aligned.m16n8k16.row.col.f32.bf16.bf16.f32 "
        "{%0,%1,%2,%3}, {%4,%5,%6,%7}, {%8,%9}, {%0,%1,%2,%3};"
        : "+f"(c[0]), "+f"(c[1]), "+f"(c[2]), "+f"(c[3])
        : "r"(a[0]), "r"(a[1]), "r"(a[2]), "r"(a[3]), "r"(b[0]), "r"(b[1]));
}
__device__ __forceinline__ float ex2(float x) {
    float y; asm("ex2.approx.ftz.f32 %0, %1;" : "=f"(y) : "f"(x)); return y;
}
// d = {hi = bf16(a), lo = bf16(b)}
__device__ __forceinline__ uint32_t cvt2(float a, float b) {
    uint32_t r; asm("cvt.rn.bf16x2.f32 %0, %1, %2;" : "=r"(r) : "f"(a), "f"(b)); return r;
}

// ============================ conversion kernels ============================
__global__ __launch_bounds__(256) void conv_x(const float* __restrict__ x) {
    int idx = blockIdx.x * 256 + threadIdx.x;          // over 8192*256
    float v = x[idx];
    int row = idx >> 8, c = idx & 255;
    __nv_bfloat16 hi = __float2bfloat16(v);
    __nv_bfloat16 lo = __float2bfloat16(v - __bfloat162float(hi));
    __nv_bfloat16* o = g_Xs + (size_t)row * KTOT;
    o[c] = hi; o[256 + c] = hi; o[512 + c] = lo;       // [hi, hi, lo]
}
__global__ __launch_bounds__(256) void conv_w(const float* __restrict__ w,
                                              __nv_bfloat16* __restrict__ o2, int n) {
    int idx = blockIdx.x * 256 + threadIdx.x;
    if (idx >= n) return;
    float v = w[idx];
    int row = idx >> 8, c = idx & 255;
    __nv_bfloat16 hi = __float2bfloat16(v);
    __nv_bfloat16 lo = __float2bfloat16(v - __bfloat162float(hi));
    __nv_bfloat16* o = o2 + (size_t)row * KTOT;
    o[c] = hi; o[256 + c] = lo; o[512 + c] = hi;       // [hi, lo, hi]
}

// ============================ HMMA GEMM (cp.async double-buffered) ============================
#define GEMM_SMEM 65536

template <int MODE>
__global__ __launch_bounds__(256, 2) void hgemm(
    const __nv_bfloat16* __restrict__ A, const __nv_bfloat16* __restrict__ B,
    const float* __restrict__ bias, float* __restrict__ C)
{
    extern __shared__ __align__(16) unsigned char dsm[];
    __shared__ float sbias[TN];
    const uint32_t sbase = smem_u32(dsm);

    const int tid = threadIdx.x, lane = tid & 31, wid = tid >> 5;
    const int warp_m = wid >> 2;
    const int warp_n = wid & 3;
    const int m0 = blockIdx.y * TM, n0 = blockIdx.x * TN;

    if (tid < TN) sbias[tid] = bias[n0 + tid];

    float acc[4][4][4];
#pragma unroll
    for (int i = 0; i < 4; i++)
#pragma unroll
        for (int j = 0; j < 4; j++)
#pragma unroll
            for (int e = 0; e < 4; e++) acc[i][j][e] = 0.f;

    const int r_ld = tid >> 3, c16 = tid & 7;
    const char* gA0 = (const char*)(A + (size_t)m0 * KTOT) + (size_t)r_ld * (KTOT * 2) + c16 * 16;
    const char* gB0 = (const char*)(B + (size_t)n0 * KTOT) + (size_t)r_ld * (KTOT * 2) + c16 * 16;

    const int arow = warp_m * 64 + (lane & 15);
    const int akb  = (lane >> 4) * 16;
    const int brow = warp_n * 32 + (lane & 7);
    const int bkb  = ((lane >> 3) & 1) * 16;

#define ISSUE_CHUNK(ch, buf)                                                         \
    do {                                                                             \
        uint32_t dA = sbase + (buf) * 32768;                                         \
        uint32_t dB = dA + 16384;                                                    \
        const char* ga = gA0 + (ch) * 128;                                           \
        const char* gb = gB0 + (ch) * 128;                                           \
        _Pragma("unroll")                                                            \
        for (int i = 0; i < 4; i++) {                                                \
            uint32_t sw = sw128((r_ld + i * 32) * 128 + c16 * 16);                   \
            asm volatile("cp.async.cg.shared.global [%0], [%1], 16;"                 \
                         :: "r"(dA + sw), "l"(ga + (size_t)i * 32 * (KTOT * 2)));    \
            asm volatile("cp.async.cg.shared.global [%0], [%1], 16;"                 \
                         :: "r"(dB + sw), "l"(gb + (size_t)i * 32 * (KTOT * 2)));    \
        }                                                                            \
        asm volatile("cp.async.commit_group;" ::: "memory");                         \
    } while (0)

    ISSUE_CHUNK(0, 0);

    for (int ch = 0; ch < NCHUNK; ch++) {
        if (ch + 1 < NCHUNK) {
            ISSUE_CHUNK(ch + 1, (ch + 1) & 1);
            asm volatile("cp.async.wait_group 1;" ::: "memory");
        } else {
            asm volatile("cp.async.wait_group 0;" ::: "memory");
        }
        __syncthreads();

        const uint32_t sA = sbase + (ch & 1) * 32768;
        const uint32_t sB = sA + 16384;
#pragma unroll
        for (int k16 = 0; k16 < 4; k16++) {
            uint32_t a[4][4], b[4][2];
#pragma unroll
            for (int mt = 0; mt < 4; mt++) {
                uint32_t addr = sA + sw128((arow + mt * 16) * 128 + k16 * 32 + akb);
                ldmx4(a[mt][0], a[mt][1], a[mt][2], a[mt][3], addr);
            }
#pragma unroll
            for (int nt = 0; nt < 4; nt++) {
                uint32_t addr = sB + sw128((brow + nt * 8) * 128 + k16 * 32 + bkb);
                ldmx2(b[nt][0], b[nt][1], addr);
            }
#pragma unroll
            for (int mt = 0; mt < 4; mt++)
#pragma unroll
                for (int nt = 0; nt < 4; nt++)
                    mma16816(acc[mt][nt], a[mt], b[nt]);
        }
        __syncthreads();
    }
#undef ISSUE_CHUNK

    // epilogue via smem staging
    float* stage = reinterpret_cast<float*>(dsm);
    const int b_idx = m0 >> 12;
    const int which = n0 >> 8;
    const float sc = (MODE == 1 && which == 0) ? 0.2550348772f : 1.0f;  // LOG2E/sqrt(32)

#pragma unroll
    for (int half = 0; half < 2; half++) {
        __syncthreads();
        if (warp_m == half) {
#pragma unroll
            for (int mt = 0; mt < 4; mt++) {
                int r0 = mt * 16 + (lane >> 2);
#pragma unroll
                for (int nt = 0; nt < 4; nt++) {
                    int cc = warp_n * 32 + nt * 8 + (lane & 3) * 2;
                    *reinterpret_cast<float2*>(&stage[r0 * 132 + cc]) =
                        make_float2(acc[mt][nt][0], acc[mt][nt][1]);
                    *reinterpret_cast<float2*>(&stage[(r0 + 8) * 132 + cc]) =
                        make_float2(acc[mt][nt][2], acc[mt][nt][3]);
                }
            }
        }
        __syncthreads();
#pragma unroll
        for (int i = 0; i < 8; i++) {
            int e = tid + 256 * i;
            int r = e >> 5, c4 = e & 31;
            float4 v;
            v.x = (stage[r * 132 + c4 * 4 + 0] + sbias[c4 * 4 + 0]) * sc;
            v.y = (stage[r * 132 + c4 * 4 + 1] + sbias[c4 * 4 + 1]) * sc;
            v.z = (stage[r * 132 + c4 * 4 + 2] + sbias[c4 * 4 + 2]) * sc;
            v.w = (stage[r * 132 + c4 * 4 + 3] + sbias[c4 * 4 + 3]) * sc;
            int grow = m0 + half * 64 + r;
            if (MODE == 1) {
                int f = n0 + c4 * 4;
                int hh = (f >> 5) & 7, d0 = f & 31;
                __nv_bfloat16* dst = (which == 0) ? g_Qb : (which == 1) ? g_Kb : g_Vb;
                int s = grow & (S_LEN - 1);
                union { __nv_bfloat16 h[4]; ull u; } H, L;
                H.h[0] = __float2bfloat16(v.x); L.h[0] = __float2bfloat16(v.x - __bfloat162float(H.h[0]));
                H.h[1] = __float2bfloat16(v.y); L.h[1] = __float2bfloat16(v.y - __bfloat162float(H.h[1]));
                H.h[2] = __float2bfloat16(v.z); L.h[2] = __float2bfloat16(v.z - __bfloat162float(H.h[2]));
                H.h[3] = __float2bfloat16(v.w); L.h[3] = __float2bfloat16(v.w - __bfloat162float(H.h[3]));
                __nv_bfloat16* p = dst + ((size_t)(b_idx * NH + hh) * S_LEN + s) * 64 + d0;
                *reinterpret_cast<ull*>(p)      = H.u;
                *reinterpret_cast<ull*>(p + 32) = L.u;
            } else {
                *reinterpret_cast<float4*>(C + (size_t)grow * EDIM + n0 + c4 * 4) = v;
            }
        }
    }
}

// ============================ banded attention (HMMA flash) ============================
// Block: 128 queries (8 warps x 16), key window 256 rows in smem.
// Each warp computes its own 144-key window (18 n-tiles of 8).
// QK: split-bf16 3 terms; P split Ph+Pl; V split [Vh|Vl] -> (Ph+Pl)@[Vh|Vl].
#define RP 144                                           // smem row pitch (bytes)
#define AT_SMEM (256 * RP + 256 * RP + 128 * RP)         // K + V + Q = 92160

__global__ __launch_bounds__(256, 2) void attn_mma()
{
    extern __shared__ __align__(16) unsigned char asmem[];
    unsigned char* sK = asmem;
    unsigned char* sV = asmem + 256 * RP;
    unsigned char* sQ = asmem + 2 * 256 * RP;
    const uint32_t uK = smem_u32(sK), uV = smem_u32(sV), uQ = smem_u32(sQ);

    const int t = threadIdx.x, lane = t & 31, w = t >> 5;
    const int q0 = blockIdx.x * 128, h = blockIdx.y, b = blockIdx.z;
    const size_t bh = (size_t)(b * NH + h) * S_LEN;
    const char* Kg = (const char*)(g_Kb + bh * 64);
    const char* Vg = (const char*)(g_Vb + bh * 64);
    const char* Qg = (const char*)(g_Qb + bh * 64);

    // async tile loads (rows = 128 bytes; clamp out-of-range keys, they get masked)
#pragma unroll
    for (int i = 0; i < 8; i++) {
        int idx = t + 256 * i, r = idx >> 3, c = idx & 7;
        int j = q0 - 64 + r; j = j < 0 ? 0 : (j > S_LEN - 1 ? S_LEN - 1 : j);
        asm volatile("cp.async.cg.shared.global [%0], [%1], 16;"
                     :: "r"(uK + r * RP + c * 16), "l"(Kg + (size_t)j * 128 + c * 16));
        asm volatile("cp.async.cg.shared.global [%0], [%1], 16;"
                     :: "r"(uV + r * RP + c * 16), "l"(Vg + (size_t)j * 128 + c * 16));
    }
#pragma unroll
    for (int i = 0; i < 4; i++) {
        int idx = t + 256 * i, r = idx >> 3, c = idx & 7;
        asm volatile("cp.async.cg.shared.global [%0], [%1], 16;"
                     :: "r"(uQ + r * RP + c * 16), "l"(Qg + (size_t)(q0 + r) * 128 + c * 16));
    }
    asm volatile("cp.async.commit_group;" ::: "memory");
    asm volatile("cp.async.wait_group 0;" ::: "memory");
    __syncthreads();

    // Q a-frags: ksteps 0,1 = Q_hi (d0-31); 2,3 = Q_lo
    uint32_t aQ[4][4];
    {
        uint32_t base = uQ + (16 * w + (lane & 15)) * RP + (lane >> 4) * 16;
#pragma unroll
        for (int ks = 0; ks < 4; ks++)
            ldmx4(aQ[ks][0], aQ[ks][1], aQ[ks][2], aQ[ks][3], base + ks * 32);
    }

    // ---- QK: S[18 tiles][4] ----
    float S[18][4];
#pragma unroll
    for (int nt = 0; nt < 18; nt++)
#pragma unroll
        for (int e = 0; e < 4; e++) S[nt][e] = 0.f;
    {
        uint32_t kb = uK + (16 * w + (lane & 7)) * RP + ((lane >> 3) & 1) * 16;
#pragma unroll
        for (int nt = 0; nt < 18; nt++) {
            uint32_t b0[2], b1[2], b2[2], b3[2];
            uint32_t ad = kb + nt * 8 * RP;
            ldmx2(b0[0], b0[1], ad);        // Kh d0-15
            ldmx2(b1[0], b1[1], ad + 32);   // Kh d16-31
            ldmx2(b2[0], b2[1], ad + 64);   // Kl d0-15
            ldmx2(b3[0], b3[1], ad + 96);   // Kl d16-31
            mma16816(S[nt], aQ[0], b0);     // hi*hi
            mma16816(S[nt], aQ[1], b1);
            mma16816(S[nt], aQ[0], b2);     // hi*lo
            mma16816(S[nt], aQ[1], b3);
            mma16816(S[nt], aQ[2], b0);     // lo*hi
            mma16816(S[nt], aQ[3], b1);
        }
    }

    // ---- mask + exp2 + row sums + P split ----
    const int gid = lane >> 2, tig = lane & 3;
    const int jwb = q0 - 64 + 16 * w;       // global key index of warp-window col 0
    float l0 = 0.f, l1 = 0.f;
    uint32_t Ph[18][2], Pl[18][2];
#pragma unroll
    for (int nt = 0; nt < 18; nt++) {
        int c0 = 8 * nt + 2 * tig, c1 = c0 + 1;
        int jg0 = jwb + c0, jg1 = jg0 + 1;
        bool in0 = (jg0 >= 0) && (jg0 < S_LEN);
        bool in1 = (jg1 >= 0) && (jg1 < S_LEN);
        bool v00 = in0 && (c0 >= gid)     && (c0 <= gid + 128);
        bool v01 = in1 && (c1 >= gid)     && (c1 <= gid + 128);
        bool v10 = in0 && (c0 >= gid + 8) && (c0 <= gid + 136);
        bool v11 = in1 && (c1 >= gid + 8) && (c1 <= gid + 136);
        float e00 = v00 ? ex2(S[nt][0]) : 0.f;
        float e01 = v01 ? ex2(S[nt][1]) : 0.f;
        float e10 = v10 ? ex2(S[nt][2]) : 0.f;
        float e11 = v11 ? ex2(S[nt][3]) : 0.f;
        l0 += e00 + e01; l1 += e10 + e11;
        uint32_t ph0 = cvt2(e01, e00);      // {hi=e01, lo=e00}
        uint32_t ph1 = cvt2(e11, e10);
        Ph[nt][0] = ph0; Ph[nt][1] = ph1;
        float pl00 = e00 - __uint_as_float(ph0 << 16);
        float pl01 = e01 - __uint_as_float(ph0 & 0xFFFF0000u);
        float pl10 = e10 - __uint_as_float(ph1 << 16);
        float pl11 = e11 - __uint_as_float(ph1 & 0xFFFF0000u);
        Pl[nt][0] = cvt2(pl01, pl00);
        Pl[nt][1] = cvt2(pl11, pl10);
    }

    // ---- PV: O[8 tiles][4]  (tiles 0-3 = Vh cols, 4-7 = Vl cols) ----
    float O[8][4];
#pragma unroll
    for (int nt = 0; nt < 8; nt++)
#pragma unroll
        for (int e = 0; e < 4; e++) O[nt][e] = 0.f;
    {
        uint32_t vb = uV + (16 * w + (lane & 15)) * RP;
#pragma unroll
        for (int kk = 0; kk < 9; kk++) {
            uint32_t aH[4] = {Ph[2 * kk][0], Ph[2 * kk][1], Ph[2 * kk + 1][0], Ph[2 * kk + 1][1]};
            uint32_t aL[4] = {Pl[2 * kk][0], Pl[2 * kk][1], Pl[2 * kk + 1][0], Pl[2 * kk + 1][1]};
            uint32_t ad = vb + kk * 16 * RP;
#pragma unroll
            for (int nt = 0; nt < 8; nt++) {
                uint32_t bv[2];
                ldmx2t(bv[0], bv[1], ad + nt * 16);
                mma16816(O[nt], aH, bv);
                mma16816(O[nt], aL, bv);
            }
        }
    }

    // ---- normalize + combine hi/lo halves ----
    l0 += __shfl_xor_sync(0xffffffffu, l0, 1);
    l0 += __shfl_xor_sync(0xffffffffu, l0, 2);
    l1 += __shfl_xor_sync(0xffffffffu, l1, 1);
    l1 += __shfl_xor_sync(0xffffffffu, l1, 2);
    const float inv0 = 1.f / l0, inv1 = 1.f / l1;

    // stage into this warp's own Q rows (pitch 36 floats); no sync needed pre-write
    float* stg = reinterpret_cast<float*>(sQ);
#pragma unroll
    for (int nt = 0; nt < 4; nt++) {
        float o0 = (O[nt][0] + O[nt + 4][0]) * inv0;
        float o1 = (O[nt][1] + O[nt + 4][1]) * inv0;
        float o2 = (O[nt][2] + O[nt + 4][2]) * inv1;
        float o3 = (O[nt][3] + O[nt + 4][3]) * inv1;
        int r0 = 16 * w + gid;
        *reinterpret_cast<float2*>(stg + r0 * 36 + 8 * nt + 2 * tig) = make_float2(o0, o1);
        *reinterpret_cast<float2*>(stg + (r0 + 8) * 36 + 8 * nt + 2 * tig) = make_float2(o2, o3);
    }
    __syncthreads();

    // coalesced [hi, hi, lo] writes into g_Os
    const int m_base = b * S_LEN + q0;
#pragma unroll
    for (int i = 0; i < 2; i++) {
        int e = t + 256 * i, r = e >> 2, c8 = e & 3;
        union { __nv_bfloat16 v[8]; uint4 u; } H, L;
#pragma unroll
        for (int jj = 0; jj < 8; jj++) {
            float v = stg[r * 36 + c8 * 8 + jj];
            __nv_bfloat16 hv = __float2bfloat16(v);
            H.v[jj] = hv;
            L.v[jj] = __float2bfloat16(v - __bfloat162float(hv));
        }
        __nv_bfloat16* orow = g_Os + (size_t)(m_base + r) * KTOT + h * HD + c8 * 8;
        *reinterpret_cast<uint4*>(orow)       = H.u;
        *reinterpret_cast<uint4*>(orow + 256) = H.u;
        *reinterpret_cast<uint4*>(orow + 512) = L.u;
    }
}

// ============================ launch ============================
extern "C" void kernel_launch(void* const* d_in, const int* in_sizes, int n_in,
                              void* d_out, int out_size)
{
    const float* x    = (const float*)d_in[0];   // [2,4096,256]
    const float* in_w = (const float*)d_in[1];   // [768,256]
    const float* in_b = (const float*)d_in[2];   // [768]
    const float* ow   = (const float*)d_in[3];   // [256,256]
    const float* ob   = (const float*)d_in[4];   // [256]
    float* out = (float*)d_out;                  // [2,4096,256]

    __nv_bfloat16 *Xs, *Os, *Win2, *Wout2;
    cudaGetSymbolAddress((void**)&Xs,    g_Xs);
    cudaGetSymbolAddress((void**)&Os,    g_Os);
    cudaGetSymbolAddress((void**)&Win2,  g_Win2);
    cudaGetSymbolAddress((void**)&Wout2, g_Wout2);

    cudaFuncSetAttribute(hgemm<1>, cudaFuncAttributeMaxDynamicSharedMemorySize, GEMM_SMEM);
    cudaFuncSetAttribute(hgemm<0>, cudaFuncAttributeMaxDynamicSharedMemorySize, GEMM_SMEM);
    cudaFuncSetAttribute(attn_mma, cudaFuncAttributeMaxDynamicSharedMemorySize, AT_SMEM);

    // 0) split-bf16 conversions
    conv_x<<<(BATCH * S_LEN * EDIM) / 256, 256>>>(x);
    conv_w<<<(3 * EDIM * EDIM + 255) / 256, 256>>>(in_w, Win2, 3 * EDIM * EDIM);
    conv_w<<<(EDIM * EDIM + 255) / 256, 256>>>(ow, Wout2, EDIM * EDIM);

    // 1) QKV projection -> g_Qb/g_Kb/g_Vb (split bf16, Q pre-scaled)
    {
        dim3 grid(3 * EDIM / TN, BATCH * S_LEN / TM);   // (6, 64)
        hgemm<1><<<grid, 256, GEMM_SMEM>>>(Xs, Win2, in_b, nullptr);
    }

    // 2) banded flash attention (HMMA) -> g_Os (bf16 augmented)
    {
        dim3 grid(S_LEN / 128, NH, BATCH);              // (32, 8, 2)
        attn_mma<<<grid, 256, AT_SMEM>>>();
    }

    // 3) output projection -> out
    {
        dim3 grid(EDIM / TN, BATCH * S_LEN / TM);       // (2, 64)
        hgemm<0><<<grid, 256, GEMM_SMEM>>>(Os, Wout2, ob, out);
    }
}

// round 6
// speedup vs baseline: 3.9463x; 1.0789x over previous
#include <cuda_runtime.h>
#include <cuda_bf16.h>
#include <math.h>
#include <stdint.h>

#define S_LEN  4096
#define BATCH  2
#define NH     8
#define HD     32
#define EDIM   256
#define WIN    64

#define KTOT   768        // augmented K for projections: [hi|hi|lo] vs [hi|lo|hi]
#define CH     64
#define NCHUNK (KTOT / CH)
#define TM     128
#define TN     128

typedef unsigned long long ull;

// ---- scratch (__device__ globals; no allocation allowed) ----
__device__ __nv_bfloat16 g_Qb[BATCH * NH * S_LEN * 64];  // [hi(32)|lo(32)], scaled LOG2E/sqrt(32)
__device__ __nv_bfloat16 g_Kb[BATCH * NH * S_LEN * 64];  // [hi|lo]
__device__ __nv_bfloat16 g_Vb[BATCH * NH * S_LEN * 64];  // [hi|lo]
__device__ __nv_bfloat16 g_Xs  [BATCH * S_LEN * KTOT];   // x        -> [hi, hi, lo]
__device__ __nv_bfloat16 g_Os  [BATCH * S_LEN * KTOT];   // attn out -> [hi, hi, lo]
__device__ __nv_bfloat16 g_Win2 [3 * EDIM * KTOT];       // in_proj_w -> [hi, lo, hi]
__device__ __nv_bfloat16 g_Wout2[EDIM * KTOT];           // out_w     -> [hi, lo, hi]

// ============================ helpers ============================
__device__ __forceinline__ uint32_t smem_u32(const void* p) {
    uint32_t a;
    asm("{ .reg .u64 t; cvta.to.shared.u64 t, %1; cvt.u32.u64 %0, t; }" : "=r"(a) : "l"(p));
    return a;
}
__device__ __forceinline__ uint32_t sw128(uint32_t off) {
    return off ^ ((off >> 3) & 0x70);
}
__device__ __forceinline__ void ldmx4(uint32_t& r0, uint32_t& r1, uint32_t& r2, uint32_t& r3,
                                      uint32_t addr) {
    asm volatile("ldmatrix.sync.aligned.m8n8.x4.shared.b16 {%0,%1,%2,%3}, [%4];"
                 : "=r"(r0), "=r"(r1), "=r"(r2), "=r"(r3) : "r"(addr));
}
__device__ __forceinline__ void ldmx4t(uint32_t& r0, uint32_t& r1, uint32_t& r2, uint32_t& r3,
                                       uint32_t addr) {
    asm volatile("ldmatrix.sync.aligned.m8n8.x4.trans.shared.b16 {%0,%1,%2,%3}, [%4];"
                 : "=r"(r0), "=r"(r1), "=r"(r2), "=r"(r3) : "r"(addr));
}
__device__ __forceinline__ void mma16816(float* c, const uint32_t* a, const uint32_t* b) {
    asm volatile(
        "mma.sync.aligned.m16n8k16.row.col.f32.bf16.bf16.f32 "
        "{%0,%1,%2,%3}, {%4,%5,%6,%7}, {%8,%9}, {%0,%1,%2,%3};"
        : "+f"(c[0]), "+f"(c[1]), "+f"(c[2]), "+f"(c[3])
        : "r"(a[0]), "r"(a[1]), "r"(a[2]), "r"(a[3]), "r"(b[0]), "r"(b[1]));
}
__device__ __forceinline__ float ex2(float x) {
    float y; asm("ex2.approx.ftz.f32 %0, %1;" : "=f"(y) : "f"(x)); return y;
}
// d = {hi = bf16(a), lo = bf16(b)}
__device__ __forceinline__ uint32_t cvt2(float a, float b) {
    uint32_t r; asm("cvt.rn.bf16x2.f32 %0, %1, %2;" : "=r"(r) : "f"(a), "f"(b)); return r;
}

// ============================ conversion kernels ============================
__global__ __launch_bounds__(256) void conv_x(const float* __restrict__ x) {
    int idx = blockIdx.x * 256 + threadIdx.x;          // over 8192*256
    float v = x[idx];
    int row = idx >> 8, c = idx & 255;
    __nv_bfloat16 hi = __float2bfloat16(v);
    __nv_bfloat16 lo = __float2bfloat16(v - __bfloat162float(hi));
    __nv_bfloat16* o = g_Xs + (size_t)row * KTOT;
    o[c] = hi; o[256 + c] = hi; o[512 + c] = lo;       // [hi, hi, lo]
}
__global__ __launch_bounds__(256) void conv_w(const float* __restrict__ w,
                                              __nv_bfloat16* __restrict__ o2, int n) {
    int idx = blockIdx.x * 256 + threadIdx.x;
    if (idx >= n) return;
    float v = w[idx];
    int row = idx >> 8, c = idx & 255;
    __nv_bfloat16 hi = __float2bfloat16(v);
    __nv_bfloat16 lo = __float2bfloat16(v - __bfloat162float(hi));
    __nv_bfloat16* o = o2 + (size_t)row * KTOT;
    o[c] = hi; o[256 + c] = lo; o[512 + c] = hi;       // [hi, lo, hi]
}

// ============================ HMMA GEMM (3-stage cp.async, 1 sync/chunk) ============================
#define GEMM_SMEM (3 * 32768)

template <int MODE>
__global__ __launch_bounds__(256, 2) void hgemm(
    const __nv_bfloat16* __restrict__ A, const __nv_bfloat16* __restrict__ B,
    const float* __restrict__ bias, float* __restrict__ C)
{
    extern __shared__ __align__(16) unsigned char dsm[];
    __shared__ float sbias[TN];
    const uint32_t sbase = smem_u32(dsm);

    const int tid = threadIdx.x, lane = tid & 31, wid = tid >> 5;
    const int warp_m = wid >> 2;
    const int warp_n = wid & 3;
    const int m0 = blockIdx.y * TM, n0 = blockIdx.x * TN;

    if (tid < TN) sbias[tid] = bias[n0 + tid];

    float acc[4][4][4];
#pragma unroll
    for (int i = 0; i < 4; i++)
#pragma unroll
        for (int j = 0; j < 4; j++)
#pragma unroll
            for (int e = 0; e < 4; e++) acc[i][j][e] = 0.f;

    const int r_ld = tid >> 3, c16 = tid & 7;
    const char* gA0 = (const char*)(A + (size_t)m0 * KTOT) + (size_t)r_ld * (KTOT * 2) + c16 * 16;
    const char* gB0 = (const char*)(B + (size_t)n0 * KTOT) + (size_t)r_ld * (KTOT * 2) + c16 * 16;

    // A ldmx4: rows (lane&15), col (lane>>4)*16
    const int arow = warp_m * 64 + (lane & 15);
    const int akb  = (lane >> 4) * 16;
    // B ldmx4 (two n-tiles): rows base + ((lane>>4)<<3) + (lane&7), col ((lane>>3)&1)*16
    const int brow4 = warp_n * 32 + ((lane >> 4) << 3) + (lane & 7);
    const int bkb4  = ((lane >> 3) & 1) * 16;

#define ISSUE_CHUNK(ch, buf)                                                         \
    do {                                                                             \
        uint32_t dA = sbase + (buf) * 32768;                                         \
        uint32_t dB = dA + 16384;                                                    \
        const char* ga = gA0 + (ch) * 128;                                           \
        const char* gb = gB0 + (ch) * 128;                                           \
        _Pragma("unroll")                                                            \
        for (int i = 0; i < 4; i++) {                                                \
            uint32_t sw = sw128((r_ld + i * 32) * 128 + c16 * 16);                   \
            asm volatile("cp.async.cg.shared.global [%0], [%1], 16;"                 \
                         :: "r"(dA + sw), "l"(ga + (size_t)i * 32 * (KTOT * 2)));    \
            asm volatile("cp.async.cg.shared.global [%0], [%1], 16;"                 \
                         :: "r"(dB + sw), "l"(gb + (size_t)i * 32 * (KTOT * 2)));    \
        }                                                                            \
        asm volatile("cp.async.commit_group;" ::: "memory");                         \
    } while (0)

    ISSUE_CHUNK(0, 0);
    ISSUE_CHUNK(1, 1);

#pragma unroll
    for (int ch = 0; ch < NCHUNK; ch++) {
        if (ch + 1 < NCHUNK)
            asm volatile("cp.async.wait_group 1;" ::: "memory");
        else
            asm volatile("cp.async.wait_group 0;" ::: "memory");
        __syncthreads();
        // fill 2 ahead: stage (ch+2)%3 == (ch-1)%3, whose readers all passed the barrier
        if (ch + 2 < NCHUNK) ISSUE_CHUNK(ch + 2, (ch + 2) % 3);

        const uint32_t sA = sbase + (ch % 3) * 32768;
        const uint32_t sB = sA + 16384;
#pragma unroll
        for (int k16 = 0; k16 < 4; k16++) {
            uint32_t a[4][4], b[4][2];
#pragma unroll
            for (int mt = 0; mt < 4; mt++) {
                uint32_t addr = sA + sw128((arow + mt * 16) * 128 + k16 * 32 + akb);
                ldmx4(a[mt][0], a[mt][1], a[mt][2], a[mt][3], addr);
            }
#pragma unroll
            for (int np = 0; np < 2; np++) {
                uint32_t addr = sB + sw128((brow4 + np * 16) * 128 + k16 * 32 + bkb4);
                ldmx4(b[2 * np][0], b[2 * np][1], b[2 * np + 1][0], b[2 * np + 1][1], addr);
            }
#pragma unroll
            for (int mt = 0; mt < 4; mt++)
#pragma unroll
                for (int nt = 0; nt < 4; nt++)
                    mma16816(acc[mt][nt], a[mt], b[nt]);
        }
    }
#undef ISSUE_CHUNK

    // epilogue via smem staging
    float* stage = reinterpret_cast<float*>(dsm);
    const int b_idx = m0 >> 12;
    const int which = n0 >> 8;
    const float sc = (MODE == 1 && which == 0) ? 0.2550348772f : 1.0f;  // LOG2E/sqrt(32)

#pragma unroll
    for (int half = 0; half < 2; half++) {
        __syncthreads();
        if (warp_m == half) {
#pragma unroll
            for (int mt = 0; mt < 4; mt++) {
                int r0 = mt * 16 + (lane >> 2);
#pragma unroll
                for (int nt = 0; nt < 4; nt++) {
                    int cc = warp_n * 32 + nt * 8 + (lane & 3) * 2;
                    *reinterpret_cast<float2*>(&stage[r0 * 132 + cc]) =
                        make_float2(acc[mt][nt][0], acc[mt][nt][1]);
                    *reinterpret_cast<float2*>(&stage[(r0 + 8) * 132 + cc]) =
                        make_float2(acc[mt][nt][2], acc[mt][nt][3]);
                }
            }
        }
        __syncthreads();
#pragma unroll
        for (int i = 0; i < 8; i++) {
            int e = tid + 256 * i;
            int r = e >> 5, c4 = e & 31;
            float4 v;
            v.x = (stage[r * 132 + c4 * 4 + 0] + sbias[c4 * 4 + 0]) * sc;
            v.y = (stage[r * 132 + c4 * 4 + 1] + sbias[c4 * 4 + 1]) * sc;
            v.z = (stage[r * 132 + c4 * 4 + 2] + sbias[c4 * 4 + 2]) * sc;
            v.w = (stage[r * 132 + c4 * 4 + 3] + sbias[c4 * 4 + 3]) * sc;
            int grow = m0 + half * 64 + r;
            if (MODE == 1) {
                int f = n0 + c4 * 4;
                int hh = (f >> 5) & 7, d0 = f & 31;
                __nv_bfloat16* dst = (which == 0) ? g_Qb : (which == 1) ? g_Kb : g_Vb;
                int s = grow & (S_LEN - 1);
                union { __nv_bfloat16 h[4]; ull u; } H, L;
                H.h[0] = __float2bfloat16(v.x); L.h[0] = __float2bfloat16(v.x - __bfloat162float(H.h[0]));
                H.h[1] = __float2bfloat16(v.y); L.h[1] = __float2bfloat16(v.y - __bfloat162float(H.h[1]));
                H.h[2] = __float2bfloat16(v.z); L.h[2] = __float2bfloat16(v.z - __bfloat162float(H.h[2]));
                H.h[3] = __float2bfloat16(v.w); L.h[3] = __float2bfloat16(v.w - __bfloat162float(H.h[3]));
                __nv_bfloat16* p = dst + ((size_t)(b_idx * NH + hh) * S_LEN + s) * 64 + d0;
                *reinterpret_cast<ull*>(p)      = H.u;
                *reinterpret_cast<ull*>(p + 32) = L.u;
            } else {
                *reinterpret_cast<float4*>(C + (size_t)grow * EDIM + n0 + c4 * 4) = v;
            }
        }
    }
}

// ============================ banded attention (HMMA flash) ============================
// Block: 128 queries (8 warps x 16), key window 256 rows in smem.
// Each warp computes its own 144-key window (18 n-tiles, processed as 9 pairs).
// QK: split-bf16 3 terms; P split Ph+Pl; V split [Vh|Vl]; Pl@Vl dropped (~2^-18).
#define RP 144                                           // smem row pitch (bytes)
#define AT_SMEM (256 * RP + 256 * RP + 128 * RP)         // K + V + Q = 92160

__global__ __launch_bounds__(256, 2) void attn_mma()
{
    extern __shared__ __align__(16) unsigned char asmem[];
    unsigned char* sK = asmem;
    unsigned char* sV = asmem + 256 * RP;
    unsigned char* sQ = asmem + 2 * 256 * RP;
    const uint32_t uK = smem_u32(sK), uV = smem_u32(sV), uQ = smem_u32(sQ);

    const int t = threadIdx.x, lane = t & 31, w = t >> 5;
    const int q0 = blockIdx.x * 128, h = blockIdx.y, b = blockIdx.z;
    const size_t bh = (size_t)(b * NH + h) * S_LEN;
    const char* Kg = (const char*)(g_Kb + bh * 64);
    const char* Vg = (const char*)(g_Vb + bh * 64);
    const char* Qg = (const char*)(g_Qb + bh * 64);

    // async tile loads (rows = 128 bytes; clamp out-of-range keys, they get masked)
#pragma unroll
    for (int i = 0; i < 8; i++) {
        int idx = t + 256 * i, r = idx >> 3, c = idx & 7;
        int j = q0 - 64 + r; j = j < 0 ? 0 : (j > S_LEN - 1 ? S_LEN - 1 : j);
        asm volatile("cp.async.cg.shared.global [%0], [%1], 16;"
                     :: "r"(uK + r * RP + c * 16), "l"(Kg + (size_t)j * 128 + c * 16));
        asm volatile("cp.async.cg.shared.global [%0], [%1], 16;"
                     :: "r"(uV + r * RP + c * 16), "l"(Vg + (size_t)j * 128 + c * 16));
    }
#pragma unroll
    for (int i = 0; i < 4; i++) {
        int idx = t + 256 * i, r = idx >> 3, c = idx & 7;
        asm volatile("cp.async.cg.shared.global [%0], [%1], 16;"
                     :: "r"(uQ + r * RP + c * 16), "l"(Qg + (size_t)(q0 + r) * 128 + c * 16));
    }
    asm volatile("cp.async.commit_group;" ::: "memory");
    asm volatile("cp.async.wait_group 0;" ::: "memory");
    __syncthreads();

    // Q a-frags: ksteps 0,1 = Q_hi (d0-31); 2,3 = Q_lo
    uint32_t aQ[4][4];
    {
        uint32_t base = uQ + (16 * w + (lane & 15)) * RP + (lane >> 4) * 16;
#pragma unroll
        for (int ks = 0; ks < 4; ks++)
            ldmx4(aQ[ks][0], aQ[ks][1], aQ[ks][2], aQ[ks][3], base + ks * 32);
    }

    // ---- QK: S[18 tiles][4], processed as 9 nt-pairs via ldmx4 ----
    float S[18][4];
#pragma unroll
    for (int nt = 0; nt < 18; nt++)
#pragma unroll
        for (int e = 0; e < 4; e++) S[nt][e] = 0.f;
    {
        // rows: 16w + ((lane>>4)<<3) + (lane&7), col sel ((lane>>3)&1)*16
        uint32_t kb4 = uK + (16 * w + ((lane >> 4) << 3) + (lane & 7)) * RP
                     + ((lane >> 3) & 1) * 16;
#pragma unroll
        for (int ntp = 0; ntp < 9; ntp++) {
            uint32_t ad = kb4 + ntp * 16 * RP;
            uint32_t h0[4], h1[4], l0[4], l1[4];
            ldmx4(h0[0], h0[1], h0[2], h0[3], ad);        // Kh d0-15  (both nts)
            ldmx4(h1[0], h1[1], h1[2], h1[3], ad + 32);   // Kh d16-31
            ldmx4(l0[0], l0[1], l0[2], l0[3], ad + 64);   // Kl d0-15
            ldmx4(l1[0], l1[1], l1[2], l1[3], ad + 96);   // Kl d16-31
            float* s0 = S[2 * ntp];
            float* s1 = S[2 * ntp + 1];
            mma16816(s0, aQ[0], h0);     mma16816(s1, aQ[0], h0 + 2);   // hi*hi
            mma16816(s0, aQ[1], h1);     mma16816(s1, aQ[1], h1 + 2);
            mma16816(s0, aQ[0], l0);     mma16816(s1, aQ[0], l0 + 2);   // hi*lo
            mma16816(s0, aQ[1], l1);     mma16816(s1, aQ[1], l1 + 2);
            mma16816(s0, aQ[2], h0);     mma16816(s1, aQ[2], h0 + 2);   // lo*hi
            mma16816(s0, aQ[3], h1);     mma16816(s1, aQ[3], h1 + 2);
        }
    }

    // ---- mask + exp2 + row sums + P split ----
    const int gid = lane >> 2, tig = lane & 3;
    const int jwb = q0 - 64 + 16 * w;       // global key index of warp-window col 0
    float l0s = 0.f, l1s = 0.f;
    uint32_t Ph[18][2], Pl[18][2];
#pragma unroll
    for (int nt = 0; nt < 18; nt++) {
        int c0 = 8 * nt + 2 * tig, c1 = c0 + 1;
        int jg0 = jwb + c0, jg1 = jg0 + 1;
        bool in0 = (jg0 >= 0) && (jg0 < S_LEN);
        bool in1 = (jg1 >= 0) && (jg1 < S_LEN);
        bool v00 = in0 && (c0 >= gid)     && (c0 <= gid + 128);
        bool v01 = in1 && (c1 >= gid)     && (c1 <= gid + 128);
        bool v10 = in0 && (c0 >= gid + 8) && (c0 <= gid + 136);
        bool v11 = in1 && (c1 >= gid + 8) && (c1 <= gid + 136);
        float e00 = v00 ? ex2(S[nt][0]) : 0.f;
        float e01 = v01 ? ex2(S[nt][1]) : 0.f;
        float e10 = v10 ? ex2(S[nt][2]) : 0.f;
        float e11 = v11 ? ex2(S[nt][3]) : 0.f;
        l0s += e00 + e01; l1s += e10 + e11;
        uint32_t ph0 = cvt2(e01, e00);      // {hi=e01, lo=e00}
        uint32_t ph1 = cvt2(e11, e10);
        Ph[nt][0] = ph0; Ph[nt][1] = ph1;
        float pl00 = e00 - __uint_as_float(ph0 << 16);
        float pl01 = e01 - __uint_as_float(ph0 & 0xFFFF0000u);
        float pl10 = e10 - __uint_as_float(ph1 << 16);
        float pl11 = e11 - __uint_as_float(ph1 & 0xFFFF0000u);
        Pl[nt][0] = cvt2(pl01, pl00);
        Pl[nt][1] = cvt2(pl11, pl10);
    }

    // ---- PV: O[8 tiles][4]  (0-3 = Vh cols, 4-7 = Vl cols; Pl only against Vh) ----
    float O[8][4];
#pragma unroll
    for (int nt = 0; nt < 8; nt++)
#pragma unroll
        for (int e = 0; e < 4; e++) O[nt][e] = 0.f;
    {
        // x4 trans: rows (lane&15), col sel (lane>>4)*16
        uint32_t vb4 = uV + (16 * w + (lane & 15)) * RP + (lane >> 4) * 16;
#pragma unroll
        for (int kk = 0; kk < 9; kk++) {
            uint32_t aH[4] = {Ph[2 * kk][0], Ph[2 * kk][1], Ph[2 * kk + 1][0], Ph[2 * kk + 1][1]};
            uint32_t aL[4] = {Pl[2 * kk][0], Pl[2 * kk][1], Pl[2 * kk + 1][0], Pl[2 * kk + 1][1]};
            uint32_t rad = vb4 + kk * 16 * RP;
#pragma unroll
            for (int nt2 = 0; nt2 < 4; nt2++) {           // nt pair: tiles 2nt2, 2nt2+1
                uint32_t v4[4];
                ldmx4t(v4[0], v4[1], v4[2], v4[3], rad + nt2 * 32);
                mma16816(O[2 * nt2],     aH, v4);
                mma16816(O[2 * nt2 + 1], aH, v4 + 2);
                if (nt2 < 2) {                             // Vh only
                    mma16816(O[2 * nt2],     aL, v4);
                    mma16816(O[2 * nt2 + 1], aL, v4 + 2);
                }
            }
        }
    }

    // ---- normalize + combine hi/lo halves ----
    l0s += __shfl_xor_sync(0xffffffffu, l0s, 1);
    l0s += __shfl_xor_sync(0xffffffffu, l0s, 2);
    l1s += __shfl_xor_sync(0xffffffffu, l1s, 1);
    l1s += __shfl_xor_sync(0xffffffffu, l1s, 2);
    const float inv0 = 1.f / l0s, inv1 = 1.f / l1s;

    // stage into this warp's own Q rows (pitch 36 floats)
    float* stg = reinterpret_cast<float*>(sQ);
#pragma unroll
    for (int nt = 0; nt < 4; nt++) {
        float o0 = (O[nt][0] + O[nt + 4][0]) * inv0;
        float o1 = (O[nt][1] + O[nt + 4][1]) * inv0;
        float o2 = (O[nt][2] + O[nt + 4][2]) * inv1;
        float o3 = (O[nt][3] + O[nt + 4][3]) * inv1;
        int r0 = 16 * w + gid;
        *reinterpret_cast<float2*>(stg + r0 * 36 + 8 * nt + 2 * tig) = make_float2(o0, o1);
        *reinterpret_cast<float2*>(stg + (r0 + 8) * 36 + 8 * nt + 2 * tig) = make_float2(o2, o3);
    }
    __syncthreads();

    // coalesced [hi, hi, lo] writes into g_Os
    const int m_base = b * S_LEN + q0;
#pragma unroll
    for (int i = 0; i < 2; i++) {
        int e = t + 256 * i, r = e >> 2, c8 = e & 3;
        union { __nv_bfloat16 v[8]; uint4 u; } H, L;
#pragma unroll
        for (int jj = 0; jj < 8; jj++) {
            float v = stg[r * 36 + c8 * 8 + jj];
            __nv_bfloat16 hv = __float2bfloat16(v);
            H.v[jj] = hv;
            L.v[jj] = __float2bfloat16(v - __bfloat162float(hv));
        }
        __nv_bfloat16* orow = g_Os + (size_t)(m_base + r) * KTOT + h * HD + c8 * 8;
        *reinterpret_cast<uint4*>(orow)       = H.u;
        *reinterpret_cast<uint4*>(orow + 256) = H.u;
        *reinterpret_cast<uint4*>(orow + 512) = L.u;
    }
}

// ============================ launch ============================
extern "C" void kernel_launch(void* const* d_in, const int* in_sizes, int n_in,
                              void* d_out, int out_size)
{
    const float* x    = (const float*)d_in[0];   // [2,4096,256]
    const float* in_w = (const float*)d_in[1];   // [768,256]
    const float* in_b = (const float*)d_in[2];   // [768]
    const float* ow   = (const float*)d_in[3];   // [256,256]
    const float* ob   = (const float*)d_in[4];   // [256]
    float* out = (float*)d_out;                  // [2,4096,256]

    __nv_bfloat16 *Xs, *Os, *Win2, *Wout2;
    cudaGetSymbolAddress((void**)&Xs,    g_Xs);
    cudaGetSymbolAddress((void**)&Os,    g_Os);
    cudaGetSymbolAddress((void**)&Win2,  g_Win2);
    cudaGetSymbolAddress((void**)&Wout2, g_Wout2);

    cudaFuncSetAttribute(hgemm<1>, cudaFuncAttributeMaxDynamicSharedMemorySize, GEMM_SMEM);
    cudaFuncSetAttribute(hgemm<0>, cudaFuncAttributeMaxDynamicSharedMemorySize, GEMM_SMEM);
    cudaFuncSetAttribute(attn_mma, cudaFuncAttributeMaxDynamicSharedMemorySize, AT_SMEM);

    // 0) split-bf16 conversions
    conv_x<<<(BATCH * S_LEN * EDIM) / 256, 256>>>(x);
    conv_w<<<(3 * EDIM * EDIM + 255) / 256, 256>>>(in_w, Win2, 3 * EDIM * EDIM);
    conv_w<<<(EDIM * EDIM + 255) / 256, 256>>>(ow, Wout2, EDIM * EDIM);

    // 1) QKV projection -> g_Qb/g_Kb/g_Vb (split bf16, Q pre-scaled)
    {
        dim3 grid(3 * EDIM / TN, BATCH * S_LEN / TM);   // (6, 64)
        hgemm<1><<<grid, 256, GEMM_SMEM>>>(Xs, Win2, in_b, nullptr);
    }

    // 2) banded flash attention (HMMA) -> g_Os (bf16 augmented)
    {
        dim3 grid(S_LEN / 128, NH, BATCH);              // (32, 8, 2)
        attn_mma<<<grid, 256, AT_SMEM>>>();
    }

    // 3) output projection -> out
    {
        dim3 grid(EDIM / TN, BATCH * S_LEN / TM);       // (2, 64)
        hgemm<0><<<grid, 256, GEMM_SMEM>>>(Os, Wout2, ob, out);
    }
}

// round 8
// speedup vs baseline: 4.6616x; 1.1812x over previous
#include <cuda_runtime.h>
#include <cuda_bf16.h>
#include <cuda_fp16.h>
#include <math.h>
#include <stdint.h>

#define S_LEN  4096
#define BATCH  2
#define NH     8
#define HD     32
#define EDIM   256
#define WIN    64

#define KTOT   512        // augmented K for projections: [x_hi|x_lo] vs [w16|w16] (fp16)
#define CH     64
#define NCHUNK (KTOT / CH)
#define TM     128
#define TN     128

typedef unsigned long long ull;

// ---- scratch (__device__ globals; no allocation allowed) ----
__device__ __nv_bfloat16 g_Qb[BATCH * NH * S_LEN * 64];  // [hi(32)|lo(32)] bf16, scaled LOG2E/sqrt(32)
__device__ __nv_bfloat16 g_Kb[BATCH * NH * S_LEN * 64];  // [hi|lo] bf16
__device__ __nv_bfloat16 g_Vb[BATCH * NH * S_LEN * 64];  // [hi|lo] bf16
__device__ __half g_Xs  [BATCH * S_LEN * KTOT];          // x        -> [hi16, lo16]
__device__ __half g_Os  [BATCH * S_LEN * KTOT];          // attn out -> [hi16, lo16]
__device__ __half g_Win2 [3 * EDIM * KTOT];              // in_proj_w -> [w16, w16]
__device__ __half g_Wout2[EDIM * KTOT];                  // out_w     -> [w16, w16]

// ============================ helpers ============================
__device__ __forceinline__ uint32_t smem_u32(const void* p) {
    uint32_t a;
    asm("{ .reg .u64 t; cvta.to.shared.u64 t, %1; cvt.u32.u64 %0, t; }" : "=r"(a) : "l"(p));
    return a;
}
__device__ __forceinline__ uint32_t sw128(uint32_t off) {
    return off ^ ((off >> 3) & 0x70);
}
__device__ __forceinline__ void ldmx4(uint32_t& r0, uint32_t& r1, uint32_t& r2, uint32_t& r3,
                                      uint32_t addr) {
    asm volatile("ldmatrix.sync.aligned.m8n8.x4.shared.b16 {%0,%1,%2,%3}, [%4];"
                 : "=r"(r0), "=r"(r1), "=r"(r2), "=r"(r3) : "r"(addr));
}
__device__ __forceinline__ void ldmx4t(uint32_t& r0, uint32_t& r1, uint32_t& r2, uint32_t& r3,
                                       uint32_t addr) {
    asm volatile("ldmatrix.sync.aligned.m8n8.x4.trans.shared.b16 {%0,%1,%2,%3}, [%4];"
                 : "=r"(r0), "=r"(r1), "=r"(r2), "=r"(r3) : "r"(addr));
}
// bf16 mma (attention)
__device__ __forceinline__ void mma16816(float* c, const uint32_t* a, const uint32_t* b) {
    asm volatile(
        "mma.sync.aligned.m16n8k16.row.col.f32.bf16.bf16.f32 "
        "{%0,%1,%2,%3}, {%4,%5,%6,%7}, {%8,%9}, {%0,%1,%2,%3};"
        : "+f"(c[0]), "+f"(c[1]), "+f"(c[2]), "+f"(c[3])
        : "r"(a[0]), "r"(a[1]), "r"(a[2]), "r"(a[3]), "r"(b[0]), "r"(b[1]));
}
// fp16 mma (projections)
__device__ __forceinline__ void mma16816h(float* c, const uint32_t* a, const uint32_t* b) {
    asm volatile(
        "mma.sync.aligned.m16n8k16.row.col.f32.f16.f16.f32 "
        "{%0,%1,%2,%3}, {%4,%5,%6,%7}, {%8,%9}, {%0,%1,%2,%3};"
        : "+f"(c[0]), "+f"(c[1]), "+f"(c[2]), "+f"(c[3])
        : "r"(a[0]), "r"(a[1]), "r"(a[2]), "r"(a[3]), "r"(b[0]), "r"(b[1]));
}
__device__ __forceinline__ float ex2(float x) {
    float y; asm("ex2.approx.ftz.f32 %0, %1;" : "=f"(y) : "f"(x)); return y;
}
// d = {hi = bf16(a), lo = bf16(b)}
__device__ __forceinline__ uint32_t cvt2(float a, float b) {
    uint32_t r; asm("cvt.rn.bf16x2.f32 %0, %1, %2;" : "=r"(r) : "f"(a), "f"(b)); return r;
}

// ============================ conversion kernels ============================
__global__ __launch_bounds__(256) void conv_x(const float* __restrict__ x) {
    int idx = blockIdx.x * 256 + threadIdx.x;          // over 8192*256
    float v = x[idx];
    int row = idx >> 8, c = idx & 255;
    __half hi = __float2half_rn(v);
    __half lo = __float2half_rn(v - __half2float(hi));
    __half* o = g_Xs + (size_t)row * KTOT;
    o[c] = hi; o[256 + c] = lo;                        // [hi16, lo16]
}
__global__ __launch_bounds__(256) void conv_w(const float* __restrict__ w,
                                              __half* __restrict__ o2, int n) {
    int idx = blockIdx.x * 256 + threadIdx.x;
    if (idx >= n) return;
    float v = w[idx];
    int row = idx >> 8, c = idx & 255;
    __half w16 = __float2half_rn(v);                   // |w| <= 1/16, fp16-safe
    __half* o = o2 + (size_t)row * KTOT;
    o[c] = w16; o[256 + c] = w16;                      // [w16, w16]
}

// ============================ fp16 HMMA GEMM (3-stage cp.async) ============================
#define GEMM_SMEM (3 * 32768)

template <int MODE>
__global__ __launch_bounds__(256, 2) void hgemm(
    const __half* __restrict__ A, const __half* __restrict__ B,
    const float* __restrict__ bias, float* __restrict__ C)
{
    extern __shared__ __align__(16) unsigned char dsm[];
    __shared__ float sbias[TN];
    const uint32_t sbase = smem_u32(dsm);

    const int tid = threadIdx.x, lane = tid & 31, wid = tid >> 5;
    const int warp_m = wid >> 2;
    const int warp_n = wid & 3;
    const int m0 = blockIdx.y * TM, n0 = blockIdx.x * TN;

    if (tid < TN) sbias[tid] = bias[n0 + tid];

    float acc[4][4][4];
#pragma unroll
    for (int i = 0; i < 4; i++)
#pragma unroll
        for (int j = 0; j < 4; j++)
#pragma unroll
            for (int e = 0; e < 4; e++) acc[i][j][e] = 0.f;

    const int r_ld = tid >> 3, c16 = tid & 7;
    const char* gA0 = (const char*)(A + (size_t)m0 * KTOT) + (size_t)r_ld * (KTOT * 2) + c16 * 16;
    const char* gB0 = (const char*)(B + (size_t)n0 * KTOT) + (size_t)r_ld * (KTOT * 2) + c16 * 16;

    const int arow = warp_m * 64 + (lane & 15);
    const int akb  = (lane >> 4) * 16;
    const int brow4 = warp_n * 32 + ((lane >> 4) << 3) + (lane & 7);
    const int bkb4  = ((lane >> 3) & 1) * 16;

#define ISSUE_CHUNK(ch, buf)                                                         \
    do {                                                                             \
        uint32_t dA = sbase + (buf) * 32768;                                         \
        uint32_t dB = dA + 16384;                                                    \
        const char* ga = gA0 + (ch) * 128;                                           \
        const char* gb = gB0 + (ch) * 128;                                           \
        _Pragma("unroll")                                                            \
        for (int i = 0; i < 4; i++) {                                                \
            uint32_t sw = sw128((r_ld + i * 32) * 128 + c16 * 16);                   \
            asm volatile("cp.async.cg.shared.global [%0], [%1], 16;"                 \
                         :: "r"(dA + sw), "l"(ga + (size_t)i * 32 * (KTOT * 2)));    \
            asm volatile("cp.async.cg.shared.global [%0], [%1], 16;"                 \
                         :: "r"(dB + sw), "l"(gb + (size_t)i * 32 * (KTOT * 2)));    \
        }                                                                            \
        asm volatile("cp.async.commit_group;" ::: "memory");                         \
    } while (0)

    ISSUE_CHUNK(0, 0);
    ISSUE_CHUNK(1, 1);

#pragma unroll
    for (int ch = 0; ch < NCHUNK; ch++) {
        if (ch + 1 < NCHUNK)
            asm volatile("cp.async.wait_group 1;" ::: "memory");
        else
            asm volatile("cp.async.wait_group 0;" ::: "memory");
        __syncthreads();
        if (ch + 2 < NCHUNK) ISSUE_CHUNK(ch + 2, (ch + 2) % 3);

        const uint32_t sA = sbase + (ch % 3) * 32768;
        const uint32_t sB = sA + 16384;
#pragma unroll
        for (int k16 = 0; k16 < 4; k16++) {
            uint32_t a[4][4], b[4][2];
#pragma unroll
            for (int mt = 0; mt < 4; mt++) {
                uint32_t addr = sA + sw128((arow + mt * 16) * 128 + k16 * 32 + akb);
                ldmx4(a[mt][0], a[mt][1], a[mt][2], a[mt][3], addr);
            }
#pragma unroll
            for (int np = 0; np < 2; np++) {
                uint32_t addr = sB + sw128((brow4 + np * 16) * 128 + k16 * 32 + bkb4);
                ldmx4(b[2 * np][0], b[2 * np][1], b[2 * np + 1][0], b[2 * np + 1][1], addr);
            }
#pragma unroll
            for (int mt = 0; mt < 4; mt++)
#pragma unroll
                for (int nt = 0; nt < 4; nt++)
                    mma16816h(acc[mt][nt], a[mt], b[nt]);
        }
    }
#undef ISSUE_CHUNK

    // epilogue via smem staging
    float* stage = reinterpret_cast<float*>(dsm);
    const int b_idx = m0 >> 12;
    const int which = n0 >> 8;
    const float sc = (MODE == 1 && which == 0) ? 0.2550348772f : 1.0f;  // LOG2E/sqrt(32)

#pragma unroll
    for (int half = 0; half < 2; half++) {
        __syncthreads();
        if (warp_m == half) {
#pragma unroll
            for (int mt = 0; mt < 4; mt++) {
                int r0 = mt * 16 + (lane >> 2);
#pragma unroll
                for (int nt = 0; nt < 4; nt++) {
                    int cc = warp_n * 32 + nt * 8 + (lane & 3) * 2;
                    *reinterpret_cast<float2*>(&stage[r0 * 132 + cc]) =
                        make_float2(acc[mt][nt][0], acc[mt][nt][1]);
                    *reinterpret_cast<float2*>(&stage[(r0 + 8) * 132 + cc]) =
                        make_float2(acc[mt][nt][2], acc[mt][nt][3]);
                }
            }
        }
        __syncthreads();
#pragma unroll
        for (int i = 0; i < 8; i++) {
            int e = tid + 256 * i;
            int r = e >> 5, c4 = e & 31;
            float4 v;
            v.x = (stage[r * 132 + c4 * 4 + 0] + sbias[c4 * 4 + 0]) * sc;
            v.y = (stage[r * 132 + c4 * 4 + 1] + sbias[c4 * 4 + 1]) * sc;
            v.z = (stage[r * 132 + c4 * 4 + 2] + sbias[c4 * 4 + 2]) * sc;
            v.w = (stage[r * 132 + c4 * 4 + 3] + sbias[c4 * 4 + 3]) * sc;
            int grow = m0 + half * 64 + r;
            if (MODE == 1) {
                int f = n0 + c4 * 4;
                int hh = (f >> 5) & 7, d0 = f & 31;
                __nv_bfloat16* dst = (which == 0) ? g_Qb : (which == 1) ? g_Kb : g_Vb;
                int s = grow & (S_LEN - 1);
                union { __nv_bfloat16 h[4]; ull u; } H, L;
                H.h[0] = __float2bfloat16(v.x); L.h[0] = __float2bfloat16(v.x - __bfloat162float(H.h[0]));
                H.h[1] = __float2bfloat16(v.y); L.h[1] = __float2bfloat16(v.y - __bfloat162float(H.h[1]));
                H.h[2] = __float2bfloat16(v.z); L.h[2] = __float2bfloat16(v.z - __bfloat162float(H.h[2]));
                H.h[3] = __float2bfloat16(v.w); L.h[3] = __float2bfloat16(v.w - __bfloat162float(H.h[3]));
                __nv_bfloat16* p = dst + ((size_t)(b_idx * NH + hh) * S_LEN + s) * 64 + d0;
                *reinterpret_cast<ull*>(p)      = H.u;
                *reinterpret_cast<ull*>(p + 32) = L.u;
            } else {
                *reinterpret_cast<float4*>(C + (size_t)grow * EDIM + n0 + c4 * 4) = v;
            }
        }
    }
}

// ============================ banded attention (bf16-split HMMA flash) ============================
#define RP 144                                           // smem row pitch (bytes)
#define AT_SMEM (256 * RP + 256 * RP + 128 * RP)         // K + V + Q = 92160

__global__ __launch_bounds__(256, 2) void attn_mma()
{
    extern __shared__ __align__(16) unsigned char asmem[];
    unsigned char* sK = asmem;
    unsigned char* sV = asmem + 256 * RP;
    unsigned char* sQ = asmem + 2 * 256 * RP;
    const uint32_t uK = smem_u32(sK), uV = smem_u32(sV), uQ = smem_u32(sQ);

    const int t = threadIdx.x, lane = t & 31, w = t >> 5;
    const int q0 = blockIdx.x * 128, h = blockIdx.y, b = blockIdx.z;
    const size_t bh = (size_t)(b * NH + h) * S_LEN;
    const char* Kg = (const char*)(g_Kb + bh * 64);
    const char* Vg = (const char*)(g_Vb + bh * 64);
    const char* Qg = (const char*)(g_Qb + bh * 64);

#pragma unroll
    for (int i = 0; i < 8; i++) {
        int idx = t + 256 * i, r = idx >> 3, c = idx & 7;
        int j = q0 - 64 + r; j = j < 0 ? 0 : (j > S_LEN - 1 ? S_LEN - 1 : j);
        asm volatile("cp.async.cg.shared.global [%0], [%1], 16;"
                     :: "r"(uK + r * RP + c * 16), "l"(Kg + (size_t)j * 128 + c * 16));
        asm volatile("cp.async.cg.shared.global [%0], [%1], 16;"
                     :: "r"(uV + r * RP + c * 16), "l"(Vg + (size_t)j * 128 + c * 16));
    }
#pragma unroll
    for (int i = 0; i < 4; i++) {
        int idx = t + 256 * i, r = idx >> 3, c = idx & 7;
        asm volatile("cp.async.cg.shared.global [%0], [%1], 16;"
                     :: "r"(uQ + r * RP + c * 16), "l"(Qg + (size_t)(q0 + r) * 128 + c * 16));
    }
    asm volatile("cp.async.commit_group;" ::: "memory");
    asm volatile("cp.async.wait_group 0;" ::: "memory");
    __syncthreads();

    uint32_t aQ[4][4];
    {
        uint32_t base = uQ + (16 * w + (lane & 15)) * RP + (lane >> 4) * 16;
#pragma unroll
        for (int ks = 0; ks < 4; ks++)
            ldmx4(aQ[ks][0], aQ[ks][1], aQ[ks][2], aQ[ks][3], base + ks * 32);
    }

    float S[18][4];
#pragma unroll
    for (int nt = 0; nt < 18; nt++)
#pragma unroll
        for (int e = 0; e < 4; e++) S[nt][e] = 0.f;
    {
        uint32_t kb4 = uK + (16 * w + ((lane >> 4) << 3) + (lane & 7)) * RP
                     + ((lane >> 3) & 1) * 16;
#pragma unroll
        for (int ntp = 0; ntp < 9; ntp++) {
            uint32_t ad = kb4 + ntp * 16 * RP;
            uint32_t h0[4], h1[4], l0[4], l1[4];
            ldmx4(h0[0], h0[1], h0[2], h0[3], ad);
            ldmx4(h1[0], h1[1], h1[2], h1[3], ad + 32);
            ldmx4(l0[0], l0[1], l0[2], l0[3], ad + 64);
            ldmx4(l1[0], l1[1], l1[2], l1[3], ad + 96);
            float* s0 = S[2 * ntp];
            float* s1 = S[2 * ntp + 1];
            mma16816(s0, aQ[0], h0);     mma16816(s1, aQ[0], h0 + 2);
            mma16816(s0, aQ[1], h1);     mma16816(s1, aQ[1], h1 + 2);
            mma16816(s0, aQ[0], l0);     mma16816(s1, aQ[0], l0 + 2);
            mma16816(s0, aQ[1], l1);     mma16816(s1, aQ[1], l1 + 2);
            mma16816(s0, aQ[2], h0);     mma16816(s1, aQ[2], h0 + 2);
            mma16816(s0, aQ[3], h1);     mma16816(s1, aQ[3], h1 + 2);
        }
    }

    const int gid = lane >> 2, tig = lane & 3;
    const int jwb = q0 - 64 + 16 * w;
    float l0s = 0.f, l1s = 0.f;
    uint32_t Ph[18][2], Pl[18][2];
#pragma unroll
    for (int nt = 0; nt < 18; nt++) {
        int c0 = 8 * nt + 2 * tig, c1 = c0 + 1;
        int jg0 = jwb + c0, jg1 = jg0 + 1;
        bool in0 = (jg0 >= 0) && (jg0 < S_LEN);
        bool in1 = (jg1 >= 0) && (jg1 < S_LEN);
        bool v00 = in0 && (c0 >= gid)     && (c0 <= gid + 128);
        bool v01 = in1 && (c1 >= gid)     && (c1 <= gid + 128);
        bool v10 = in0 && (c0 >= gid + 8) && (c0 <= gid + 136);
        bool v11 = in1 && (c1 >= gid + 8) && (c1 <= gid + 136);
        float e00 = v00 ? ex2(S[nt][0]) : 0.f;
        float e01 = v01 ? ex2(S[nt][1]) : 0.f;
        float e10 = v10 ? ex2(S[nt][2]) : 0.f;
        float e11 = v11 ? ex2(S[nt][3]) : 0.f;
        l0s += e00 + e01; l1s += e10 + e11;
        uint32_t ph0 = cvt2(e01, e00);
        uint32_t ph1 = cvt2(e11, e10);
        Ph[nt][0] = ph0; Ph[nt][1] = ph1;
        float pl00 = e00 - __uint_as_float(ph0 << 16);
        float pl01 = e01 - __uint_as_float(ph0 & 0xFFFF0000u);
        float pl10 = e10 - __uint_as_float(ph1 << 16);
        float pl11 = e11 - __uint_as_float(ph1 & 0xFFFF0000u);
        Pl[nt][0] = cvt2(pl01, pl00);
        Pl[nt][1] = cvt2(pl11, pl10);
    }

    float O[8][4];
#pragma unroll
    for (int nt = 0; nt < 8; nt++)
#pragma unroll
        for (int e = 0; e < 4; e++) O[nt][e] = 0.f;
    {
        uint32_t vb4 = uV + (16 * w + (lane & 15)) * RP + (lane >> 4) * 16;
#pragma unroll
        for (int kk = 0; kk < 9; kk++) {
            uint32_t aH[4] = {Ph[2 * kk][0], Ph[2 * kk][1], Ph[2 * kk + 1][0], Ph[2 * kk + 1][1]};
            uint32_t aL[4] = {Pl[2 * kk][0], Pl[2 * kk][1], Pl[2 * kk + 1][0], Pl[2 * kk + 1][1]};
            uint32_t rad = vb4 + kk * 16 * RP;
#pragma unroll
            for (int nt2 = 0; nt2 < 4; nt2++) {
                uint32_t v4[4];
                ldmx4t(v4[0], v4[1], v4[2], v4[3], rad + nt2 * 32);
                mma16816(O[2 * nt2],     aH, v4);
                mma16816(O[2 * nt2 + 1], aH, v4 + 2);
                if (nt2 < 2) {
                    mma16816(O[2 * nt2],     aL, v4);
                    mma16816(O[2 * nt2 + 1], aL, v4 + 2);
                }
            }
        }
    }

    l0s += __shfl_xor_sync(0xffffffffu, l0s, 1);
    l0s += __shfl_xor_sync(0xffffffffu, l0s, 2);
    l1s += __shfl_xor_sync(0xffffffffu, l1s, 1);
    l1s += __shfl_xor_sync(0xffffffffu, l1s, 2);
    const float inv0 = 1.f / l0s, inv1 = 1.f / l1s;

    float* stg = reinterpret_cast<float*>(sQ);
#pragma unroll
    for (int nt = 0; nt < 4; nt++) {
        float o0 = (O[nt][0] + O[nt + 4][0]) * inv0;
        float o1 = (O[nt][1] + O[nt + 4][1]) * inv0;
        float o2 = (O[nt][2] + O[nt + 4][2]) * inv1;
        float o3 = (O[nt][3] + O[nt + 4][3]) * inv1;
        int r0 = 16 * w + gid;
        *reinterpret_cast<float2*>(stg + r0 * 36 + 8 * nt + 2 * tig) = make_float2(o0, o1);
        *reinterpret_cast<float2*>(stg + (r0 + 8) * 36 + 8 * nt + 2 * tig) = make_float2(o2, o3);
    }
    __syncthreads();

    // coalesced [hi16, lo16] writes into g_Os (fp16 split for out-proj)
    const int m_base = b * S_LEN + q0;
#pragma unroll
    for (int i = 0; i < 2; i++) {
        int e = t + 256 * i, r = e >> 2, c8 = e & 3;
        union { __half v[8]; uint4 u; } H, L;
#pragma unroll
        for (int jj = 0; jj < 8; jj++) {
            float v = stg[r * 36 + c8 * 8 + jj];
            __half hv = __float2half_rn(v);
            H.v[jj] = hv;
            L.v[jj] = __float2half_rn(v - __half2float(hv));
        }
        __half* orow = g_Os + (size_t)(m_base + r) * KTOT + h * HD + c8 * 8;
        *reinterpret_cast<uint4*>(orow)       = H.u;
        *reinterpret_cast<uint4*>(orow + 256) = L.u;
    }
}

// ============================ launch ============================
extern "C" void kernel_launch(void* const* d_in, const int* in_sizes, int n_in,
                              void* d_out, int out_size)
{
    const float* x    = (const float*)d_in[0];   // [2,4096,256]
    const float* in_w = (const float*)d_in[1];   // [768,256]
    const float* in_b = (const float*)d_in[2];   // [768]
    const float* ow   = (const float*)d_in[3];   // [256,256]
    const float* ob   = (const float*)d_in[4];   // [256]
    float* out = (float*)d_out;                  // [2,4096,256]

    __half *Xs, *Os, *Win2, *Wout2;
    cudaGetSymbolAddress((void**)&Xs,    g_Xs);
    cudaGetSymbolAddress((void**)&Os,    g_Os);
    cudaGetSymbolAddress((void**)&Win2,  g_Win2);
    cudaGetSymbolAddress((void**)&Wout2, g_Wout2);

    cudaFuncSetAttribute(hgemm<1>, cudaFuncAttributeMaxDynamicSharedMemorySize, GEMM_SMEM);
    cudaFuncSetAttribute(hgemm<0>, cudaFuncAttributeMaxDynamicSharedMemorySize, GEMM_SMEM);
    cudaFuncSetAttribute(attn_mma, cudaFuncAttributeMaxDynamicSharedMemorySize, AT_SMEM);

    // 0) fp16-split conversions
    conv_x<<<(BATCH * S_LEN * EDIM) / 256, 256>>>(x);
    conv_w<<<(3 * EDIM * EDIM + 255) / 256, 256>>>(in_w, Win2, 3 * EDIM * EDIM);
    conv_w<<<(EDIM * EDIM + 255) / 256, 256>>>(ow, Wout2, EDIM * EDIM);

    // 1) QKV projection (fp16 HMMA, K=512) -> g_Qb/g_Kb/g_Vb (bf16 split, Q pre-scaled)
    {
        dim3 grid(3 * EDIM / TN, BATCH * S_LEN / TM);   // (6, 64)
        hgemm<1><<<grid, 256, GEMM_SMEM>>>(Xs, Win2, in_b, nullptr);
    }

    // 2) banded flash attention (bf16 HMMA) -> g_Os (fp16 split)
    {
        dim3 grid(S_LEN / 128, NH, BATCH);              // (32, 8, 2)
        attn_mma<<<grid, 256, AT_SMEM>>>();
    }

    // 3) output projection (fp16 HMMA, K=512) -> out
    {
        dim3 grid(EDIM / TN, BATCH * S_LEN / TM);       // (2, 64)
        hgemm<0><<<grid, 256, GEMM_SMEM>>>(Os, Wout2, ob, out);
    }
}

// round 9
// speedup vs baseline: 5.8278x; 1.2502x over previous
#include <cuda_runtime.h>
#include <cuda_bf16.h>
#include <cuda_fp16.h>
#include <math.h>
#include <stdint.h>

#define S_LEN  4096
#define BATCH  2
#define NH     8
#define HD     32
#define EDIM   256
#define WIN    64

#define KTOT   256        // plain fp16 GEMM K (no augmentation)
#define CH     64
#define NCHUNK (KTOT / CH)
#define TM     128
#define TN     128

typedef unsigned long long ull;

// ---- scratch (__device__ globals; no allocation allowed) ----
__device__ __nv_bfloat16 g_Qb[BATCH * NH * S_LEN * 64];  // [hi(32)|lo(32)] bf16, scaled LOG2E/sqrt(32)
__device__ __nv_bfloat16 g_Kb[BATCH * NH * S_LEN * 64];  // [hi|lo] bf16
__device__ __nv_bfloat16 g_Vb[BATCH * NH * S_LEN * 64];  // [hi|lo] bf16
__device__ __half g_Xs  [BATCH * S_LEN * KTOT];          // x        -> fp16
__device__ __half g_Os  [BATCH * S_LEN * KTOT];          // attn out -> fp16
__device__ __half g_Win2 [3 * EDIM * KTOT];              // in_proj_w -> fp16
__device__ __half g_Wout2[EDIM * KTOT];                  // out_w     -> fp16

// ============================ helpers ============================
__device__ __forceinline__ uint32_t smem_u32(const void* p) {
    uint32_t a;
    asm("{ .reg .u64 t; cvta.to.shared.u64 t, %1; cvt.u32.u64 %0, t; }" : "=r"(a) : "l"(p));
    return a;
}
__device__ __forceinline__ uint32_t sw128(uint32_t off) {
    return off ^ ((off >> 3) & 0x70);
}
__device__ __forceinline__ void ldmx4(uint32_t& r0, uint32_t& r1, uint32_t& r2, uint32_t& r3,
                                      uint32_t addr) {
    asm volatile("ldmatrix.sync.aligned.m8n8.x4.shared.b16 {%0,%1,%2,%3}, [%4];"
                 : "=r"(r0), "=r"(r1), "=r"(r2), "=r"(r3) : "r"(addr));
}
__device__ __forceinline__ void ldmx4t(uint32_t& r0, uint32_t& r1, uint32_t& r2, uint32_t& r3,
                                       uint32_t addr) {
    asm volatile("ldmatrix.sync.aligned.m8n8.x4.trans.shared.b16 {%0,%1,%2,%3}, [%4];"
                 : "=r"(r0), "=r"(r1), "=r"(r2), "=r"(r3) : "r"(addr));
}
// bf16 mma (attention)
__device__ __forceinline__ void mma16816(float* c, const uint32_t* a, const uint32_t* b) {
    asm volatile(
        "mma.sync.aligned.m16n8k16.row.col.f32.bf16.bf16.f32 "
        "{%0,%1,%2,%3}, {%4,%5,%6,%7}, {%8,%9}, {%0,%1,%2,%3};"
        : "+f"(c[0]), "+f"(c[1]), "+f"(c[2]), "+f"(c[3])
        : "r"(a[0]), "r"(a[1]), "r"(a[2]), "r"(a[3]), "r"(b[0]), "r"(b[1]));
}
// fp16 mma (projections)
__device__ __forceinline__ void mma16816h(float* c, const uint32_t* a, const uint32_t* b) {
    asm volatile(
        "mma.sync.aligned.m16n8k16.row.col.f32.f16.f16.f32 "
        "{%0,%1,%2,%3}, {%4,%5,%6,%7}, {%8,%9}, {%0,%1,%2,%3};"
        : "+f"(c[0]), "+f"(c[1]), "+f"(c[2]), "+f"(c[3])
        : "r"(a[0]), "r"(a[1]), "r"(a[2]), "r"(a[3]), "r"(b[0]), "r"(b[1]));
}
__device__ __forceinline__ float ex2(float x) {
    float y; asm("ex2.approx.ftz.f32 %0, %1;" : "=f"(y) : "f"(x)); return y;
}
// d = {hi = bf16(a), lo = bf16(b)}
__device__ __forceinline__ uint32_t cvt2(float a, float b) {
    uint32_t r; asm("cvt.rn.bf16x2.f32 %0, %1, %2;" : "=r"(r) : "f"(a), "f"(b)); return r;
}

// ============================ conversion kernels ============================
__global__ __launch_bounds__(256) void conv_x(const float* __restrict__ x) {
    int idx = blockIdx.x * 256 + threadIdx.x;          // over 8192*256
    g_Xs[idx] = __float2half_rn(x[idx]);
}
__global__ __launch_bounds__(256) void conv_w(const float* __restrict__ w,
                                              __half* __restrict__ o2, int n) {
    int idx = blockIdx.x * 256 + threadIdx.x;
    if (idx >= n) return;
    o2[idx] = __float2half_rn(w[idx]);
}

// ============================ fp16 HMMA GEMM (3-stage cp.async) ============================
#define GEMM_SMEM (3 * 32768)

template <int MODE>
__global__ __launch_bounds__(256, 2) void hgemm(
    const __half* __restrict__ A, const __half* __restrict__ B,
    const float* __restrict__ bias, float* __restrict__ C)
{
    extern __shared__ __align__(16) unsigned char dsm[];
    __shared__ float sbias[TN];
    const uint32_t sbase = smem_u32(dsm);

    const int tid = threadIdx.x, lane = tid & 31, wid = tid >> 5;
    const int warp_m = wid >> 2;
    const int warp_n = wid & 3;
    const int m0 = blockIdx.y * TM, n0 = blockIdx.x * TN;

    if (tid < TN) sbias[tid] = bias[n0 + tid];

    float acc[4][4][4];
#pragma unroll
    for (int i = 0; i < 4; i++)
#pragma unroll
        for (int j = 0; j < 4; j++)
#pragma unroll
            for (int e = 0; e < 4; e++) acc[i][j][e] = 0.f;

    const int r_ld = tid >> 3, c16 = tid & 7;
    const char* gA0 = (const char*)(A + (size_t)m0 * KTOT) + (size_t)r_ld * (KTOT * 2) + c16 * 16;
    const char* gB0 = (const char*)(B + (size_t)n0 * KTOT) + (size_t)r_ld * (KTOT * 2) + c16 * 16;

    const int arow = warp_m * 64 + (lane & 15);
    const int akb  = (lane >> 4) * 16;
    const int brow4 = warp_n * 32 + ((lane >> 4) << 3) + (lane & 7);
    const int bkb4  = ((lane >> 3) & 1) * 16;

#define ISSUE_CHUNK(ch, buf)                                                         \
    do {                                                                             \
        uint32_t dA = sbase + (buf) * 32768;                                         \
        uint32_t dB = dA + 16384;                                                    \
        const char* ga = gA0 + (ch) * 128;                                           \
        const char* gb = gB0 + (ch) * 128;                                           \
        _Pragma("unroll")                                                            \
        for (int i = 0; i < 4; i++) {                                                \
            uint32_t sw = sw128((r_ld + i * 32) * 128 + c16 * 16);                   \
            asm volatile("cp.async.cg.shared.global [%0], [%1], 16;"                 \
                         :: "r"(dA + sw), "l"(ga + (size_t)i * 32 * (KTOT * 2)));    \
            asm volatile("cp.async.cg.shared.global [%0], [%1], 16;"                 \
                         :: "r"(dB + sw), "l"(gb + (size_t)i * 32 * (KTOT * 2)));    \
        }                                                                            \
        asm volatile("cp.async.commit_group;" ::: "memory");                         \
    } while (0)

    ISSUE_CHUNK(0, 0);
    ISSUE_CHUNK(1, 1);

#pragma unroll
    for (int ch = 0; ch < NCHUNK; ch++) {
        if (ch + 1 < NCHUNK)
            asm volatile("cp.async.wait_group 1;" ::: "memory");
        else
            asm volatile("cp.async.wait_group 0;" ::: "memory");
        __syncthreads();
        if (ch + 2 < NCHUNK) ISSUE_CHUNK(ch + 2, (ch + 2) % 3);

        const uint32_t sA = sbase + (ch % 3) * 32768;
        const uint32_t sB = sA + 16384;
#pragma unroll
        for (int k16 = 0; k16 < 4; k16++) {
            uint32_t a[4][4], b[4][2];
#pragma unroll
            for (int mt = 0; mt < 4; mt++) {
                uint32_t addr = sA + sw128((arow + mt * 16) * 128 + k16 * 32 + akb);
                ldmx4(a[mt][0], a[mt][1], a[mt][2], a[mt][3], addr);
            }
#pragma unroll
            for (int np = 0; np < 2; np++) {
                uint32_t addr = sB + sw128((brow4 + np * 16) * 128 + k16 * 32 + bkb4);
                ldmx4(b[2 * np][0], b[2 * np][1], b[2 * np + 1][0], b[2 * np + 1][1], addr);
            }
#pragma unroll
            for (int mt = 0; mt < 4; mt++)
#pragma unroll
                for (int nt = 0; nt < 4; nt++)
                    mma16816h(acc[mt][nt], a[mt], b[nt]);
        }
    }
#undef ISSUE_CHUNK

    // epilogue via smem staging
    float* stage = reinterpret_cast<float*>(dsm);
    const int b_idx = m0 >> 12;
    const int which = n0 >> 8;
    const float sc = (MODE == 1 && which == 0) ? 0.2550348772f : 1.0f;  // LOG2E/sqrt(32)

#pragma unroll
    for (int half = 0; half < 2; half++) {
        __syncthreads();
        if (warp_m == half) {
#pragma unroll
            for (int mt = 0; mt < 4; mt++) {
                int r0 = mt * 16 + (lane >> 2);
#pragma unroll
                for (int nt = 0; nt < 4; nt++) {
                    int cc = warp_n * 32 + nt * 8 + (lane & 3) * 2;
                    *reinterpret_cast<float2*>(&stage[r0 * 132 + cc]) =
                        make_float2(acc[mt][nt][0], acc[mt][nt][1]);
                    *reinterpret_cast<float2*>(&stage[(r0 + 8) * 132 + cc]) =
                        make_float2(acc[mt][nt][2], acc[mt][nt][3]);
                }
            }
        }
        __syncthreads();
#pragma unroll
        for (int i = 0; i < 8; i++) {
            int e = tid + 256 * i;
            int r = e >> 5, c4 = e & 31;
            float4 v;
            v.x = (stage[r * 132 + c4 * 4 + 0] + sbias[c4 * 4 + 0]) * sc;
            v.y = (stage[r * 132 + c4 * 4 + 1] + sbias[c4 * 4 + 1]) * sc;
            v.z = (stage[r * 132 + c4 * 4 + 2] + sbias[c4 * 4 + 2]) * sc;
            v.w = (stage[r * 132 + c4 * 4 + 3] + sbias[c4 * 4 + 3]) * sc;
            int grow = m0 + half * 64 + r;
            if (MODE == 1) {
                int f = n0 + c4 * 4;
                int hh = (f >> 5) & 7, d0 = f & 31;
                __nv_bfloat16* dst = (which == 0) ? g_Qb : (which == 1) ? g_Kb : g_Vb;
                int s = grow & (S_LEN - 1);
                union { __nv_bfloat16 h[4]; ull u; } H, L;
                H.h[0] = __float2bfloat16(v.x); L.h[0] = __float2bfloat16(v.x - __bfloat162float(H.h[0]));
                H.h[1] = __float2bfloat16(v.y); L.h[1] = __float2bfloat16(v.y - __bfloat162float(H.h[1]));
                H.h[2] = __float2bfloat16(v.z); L.h[2] = __float2bfloat16(v.z - __bfloat162float(H.h[2]));
                H.h[3] = __float2bfloat16(v.w); L.h[3] = __float2bfloat16(v.w - __bfloat162float(H.h[3]));
                __nv_bfloat16* p = dst + ((size_t)(b_idx * NH + hh) * S_LEN + s) * 64 + d0;
                *reinterpret_cast<ull*>(p)      = H.u;
                *reinterpret_cast<ull*>(p + 32) = L.u;
            } else {
                *reinterpret_cast<float4*>(C + (size_t)grow * EDIM + n0 + c4 * 4) = v;
            }
        }
    }
}

// ============================ banded attention (bf16-split HMMA flash) ============================
#define RP 144                                           // smem row pitch (bytes)
#define AT_SMEM (256 * RP + 256 * RP + 128 * RP)         // K + V + Q = 92160

__global__ __launch_bounds__(256, 2) void attn_mma()
{
    extern __shared__ __align__(16) unsigned char asmem[];
    unsigned char* sK = asmem;
    unsigned char* sV = asmem + 256 * RP;
    unsigned char* sQ = asmem + 2 * 256 * RP;
    const uint32_t uK = smem_u32(sK), uV = smem_u32(sV), uQ = smem_u32(sQ);

    const int t = threadIdx.x, lane = t & 31, w = t >> 5;
    const int q0 = blockIdx.x * 128, h = blockIdx.y, b = blockIdx.z;
    const size_t bh = (size_t)(b * NH + h) * S_LEN;
    const char* Kg = (const char*)(g_Kb + bh * 64);
    const char* Vg = (const char*)(g_Vb + bh * 64);
    const char* Qg = (const char*)(g_Qb + bh * 64);

#pragma unroll
    for (int i = 0; i < 8; i++) {
        int idx = t + 256 * i, r = idx >> 3, c = idx & 7;
        int j = q0 - 64 + r; j = j < 0 ? 0 : (j > S_LEN - 1 ? S_LEN - 1 : j);
        asm volatile("cp.async.cg.shared.global [%0], [%1], 16;"
                     :: "r"(uK + r * RP + c * 16), "l"(Kg + (size_t)j * 128 + c * 16));
        asm volatile("cp.async.cg.shared.global [%0], [%1], 16;"
                     :: "r"(uV + r * RP + c * 16), "l"(Vg + (size_t)j * 128 + c * 16));
    }
#pragma unroll
    for (int i = 0; i < 4; i++) {
        int idx = t + 256 * i, r = idx >> 3, c = idx & 7;
        asm volatile("cp.async.cg.shared.global [%0], [%1], 16;"
                     :: "r"(uQ + r * RP + c * 16), "l"(Qg + (size_t)(q0 + r) * 128 + c * 16));
    }
    asm volatile("cp.async.commit_group;" ::: "memory");
    asm volatile("cp.async.wait_group 0;" ::: "memory");
    __syncthreads();

    uint32_t aQ[4][4];
    {
        uint32_t base = uQ + (16 * w + (lane & 15)) * RP + (lane >> 4) * 16;
#pragma unroll
        for (int ks = 0; ks < 4; ks++)
            ldmx4(aQ[ks][0], aQ[ks][1], aQ[ks][2], aQ[ks][3], base + ks * 32);
    }

    float S[18][4];
#pragma unroll
    for (int nt = 0; nt < 18; nt++)
#pragma unroll
        for (int e = 0; e < 4; e++) S[nt][e] = 0.f;
    {
        uint32_t kb4 = uK + (16 * w + ((lane >> 4) << 3) + (lane & 7)) * RP
                     + ((lane >> 3) & 1) * 16;
#pragma unroll
        for (int ntp = 0; ntp < 9; ntp++) {
            uint32_t ad = kb4 + ntp * 16 * RP;
            uint32_t h0[4], h1[4], l0[4], l1[4];
            ldmx4(h0[0], h0[1], h0[2], h0[3], ad);
            ldmx4(h1[0], h1[1], h1[2], h1[3], ad + 32);
            ldmx4(l0[0], l0[1], l0[2], l0[3], ad + 64);
            ldmx4(l1[0], l1[1], l1[2], l1[3], ad + 96);
            float* s0 = S[2 * ntp];
            float* s1 = S[2 * ntp + 1];
            mma16816(s0, aQ[0], h0);     mma16816(s1, aQ[0], h0 + 2);
            mma16816(s0, aQ[1], h1);     mma16816(s1, aQ[1], h1 + 2);
            mma16816(s0, aQ[0], l0);     mma16816(s1, aQ[0], l0 + 2);
            mma16816(s0, aQ[1], l1);     mma16816(s1, aQ[1], l1 + 2);
            mma16816(s0, aQ[2], h0);     mma16816(s1, aQ[2], h0 + 2);
            mma16816(s0, aQ[3], h1);     mma16816(s1, aQ[3], h1 + 2);
        }
    }

    const int gid = lane >> 2, tig = lane & 3;
    const int jwb = q0 - 64 + 16 * w;
    float l0s = 0.f, l1s = 0.f;
    uint32_t Ph[18][2], Pl[18][2];
#pragma unroll
    for (int nt = 0; nt < 18; nt++) {
        int c0 = 8 * nt + 2 * tig, c1 = c0 + 1;
        int jg0 = jwb + c0, jg1 = jg0 + 1;
        bool in0 = (jg0 >= 0) && (jg0 < S_LEN);
        bool in1 = (jg1 >= 0) && (jg1 < S_LEN);
        bool v00 = in0 && (c0 >= gid)     && (c0 <= gid + 128);
        bool v01 = in1 && (c1 >= gid)     && (c1 <= gid + 128);
        bool v10 = in0 && (c0 >= gid + 8) && (c0 <= gid + 136);
        bool v11 = in1 && (c1 >= gid + 8) && (c1 <= gid + 136);
        float e00 = v00 ? ex2(S[nt][0]) : 0.f;
        float e01 = v01 ? ex2(S[nt][1]) : 0.f;
        float e10 = v10 ? ex2(S[nt][2]) : 0.f;
        float e11 = v11 ? ex2(S[nt][3]) : 0.f;
        l0s += e00 + e01; l1s += e10 + e11;
        uint32_t ph0 = cvt2(e01, e00);
        uint32_t ph1 = cvt2(e11, e10);
        Ph[nt][0] = ph0; Ph[nt][1] = ph1;
        float pl00 = e00 - __uint_as_float(ph0 << 16);
        float pl01 = e01 - __uint_as_float(ph0 & 0xFFFF0000u);
        float pl10 = e10 - __uint_as_float(ph1 << 16);
        float pl11 = e11 - __uint_as_float(ph1 & 0xFFFF0000u);
        Pl[nt][0] = cvt2(pl01, pl00);
        Pl[nt][1] = cvt2(pl11, pl10);
    }

    float O[8][4];
#pragma unroll
    for (int nt = 0; nt < 8; nt++)
#pragma unroll
        for (int e = 0; e < 4; e++) O[nt][e] = 0.f;
    {
        uint32_t vb4 = uV + (16 * w + (lane & 15)) * RP + (lane >> 4) * 16;
#pragma unroll
        for (int kk = 0; kk < 9; kk++) {
            uint32_t aH[4] = {Ph[2 * kk][0], Ph[2 * kk][1], Ph[2 * kk + 1][0], Ph[2 * kk + 1][1]};
            uint32_t aL[4] = {Pl[2 * kk][0], Pl[2 * kk][1], Pl[2 * kk + 1][0], Pl[2 * kk + 1][1]};
            uint32_t rad = vb4 + kk * 16 * RP;
#pragma unroll
            for (int nt2 = 0; nt2 < 4; nt2++) {
                uint32_t v4[4];
                ldmx4t(v4[0], v4[1], v4[2], v4[3], rad + nt2 * 32);
                mma16816(O[2 * nt2],     aH, v4);
                mma16816(O[2 * nt2 + 1], aH, v4 + 2);
                if (nt2 < 2) {
                    mma16816(O[2 * nt2],     aL, v4);
                    mma16816(O[2 * nt2 + 1], aL, v4 + 2);
                }
            }
        }
    }

    l0s += __shfl_xor_sync(0xffffffffu, l0s, 1);
    l0s += __shfl_xor_sync(0xffffffffu, l0s, 2);
    l1s += __shfl_xor_sync(0xffffffffu, l1s, 1);
    l1s += __shfl_xor_sync(0xffffffffu, l1s, 2);
    const float inv0 = 1.f / l0s, inv1 = 1.f / l1s;

    float* stg = reinterpret_cast<float*>(sQ);
#pragma unroll
    for (int nt = 0; nt < 4; nt++) {
        float o0 = (O[nt][0] + O[nt + 4][0]) * inv0;
        float o1 = (O[nt][1] + O[nt + 4][1]) * inv0;
        float o2 = (O[nt][2] + O[nt + 4][2]) * inv1;
        float o3 = (O[nt][3] + O[nt + 4][3]) * inv1;
        int r0 = 16 * w + gid;
        *reinterpret_cast<float2*>(stg + r0 * 36 + 8 * nt + 2 * tig) = make_float2(o0, o1);
        *reinterpret_cast<float2*>(stg + (r0 + 8) * 36 + 8 * nt + 2 * tig) = make_float2(o2, o3);
    }
    __syncthreads();

    // coalesced plain-fp16 writes into g_Os
    const int m_base = b * S_LEN + q0;
#pragma unroll
    for (int i = 0; i < 2; i++) {
        int e = t + 256 * i, r = e >> 2, c8 = e & 3;
        union { __half v[8]; uint4 u; } H;
#pragma unroll
        for (int jj = 0; jj < 8; jj++)
            H.v[jj] = __float2half_rn(stg[r * 36 + c8 * 8 + jj]);
        __half* orow = g_Os + (size_t)(m_base + r) * KTOT + h * HD + c8 * 8;
        *reinterpret_cast<uint4*>(orow) = H.u;
    }
}

// ============================ launch ============================
extern "C" void kernel_launch(void* const* d_in, const int* in_sizes, int n_in,
                              void* d_out, int out_size)
{
    const float* x    = (const float*)d_in[0];   // [2,4096,256]
    const float* in_w = (const float*)d_in[1];   // [768,256]
    const float* in_b = (const float*)d_in[2];   // [768]
    const float* ow   = (const float*)d_in[3];   // [256,256]
    const float* ob   = (const float*)d_in[4];   // [256]
    float* out = (float*)d_out;                  // [2,4096,256]

    __half *Xs, *Os, *Win2, *Wout2;
    cudaGetSymbolAddress((void**)&Xs,    g_Xs);
    cudaGetSymbolAddress((void**)&Os,    g_Os);
    cudaGetSymbolAddress((void**)&Win2,  g_Win2);
    cudaGetSymbolAddress((void**)&Wout2, g_Wout2);

    cudaFuncSetAttribute(hgemm<1>, cudaFuncAttributeMaxDynamicSharedMemorySize, GEMM_SMEM);
    cudaFuncSetAttribute(hgemm<0>, cudaFuncAttributeMaxDynamicSharedMemorySize, GEMM_SMEM);
    cudaFuncSetAttribute(attn_mma, cudaFuncAttributeMaxDynamicSharedMemorySize, AT_SMEM);

    // 0) fp16 conversions (plain casts)
    conv_x<<<(BATCH * S_LEN * EDIM) / 256, 256>>>(x);
    conv_w<<<(3 * EDIM * EDIM + 255) / 256, 256>>>(in_w, Win2, 3 * EDIM * EDIM);
    conv_w<<<(EDIM * EDIM + 255) / 256, 256>>>(ow, Wout2, EDIM * EDIM);

    // 1) QKV projection (fp16 HMMA, K=256) -> g_Qb/g_Kb/g_Vb (bf16 split, Q pre-scaled)
    {
        dim3 grid(3 * EDIM / TN, BATCH * S_LEN / TM);   // (6, 64)
        hgemm<1><<<grid, 256, GEMM_SMEM>>>(Xs, Win2, in_b, nullptr);
    }

    // 2) banded flash attention (bf16 HMMA) -> g_Os (fp16)
    {
        dim3 grid(S_LEN / 128, NH, BATCH);              // (32, 8, 2)
        attn_mma<<<grid, 256, AT_SMEM>>>();
    }

    // 3) output projection (fp16 HMMA, K=256) -> out
    {
        dim3 grid(EDIM / TN, BATCH * S_LEN / TM);       // (2, 64)
        hgemm<0><<<grid, 256, GEMM_SMEM>>>(Os, Wout2, ob, out);
    }
}

// round 11
// speedup vs baseline: 6.8244x; 1.1710x over previous
#include <cuda_runtime.h>
#include <cuda_bf16.h>
#include <cuda_fp16.h>
#include <math.h>
#include <stdint.h>

#define S_LEN  4096
#define BATCH  2
#define NH     8
#define HD     32
#define EDIM   256
#define WIN    64

#define KTOT   256        // plain fp16 GEMM K
#define CH     64
#define NCHUNK (KTOT / CH)
#define TM     128
#define TN     128

typedef unsigned long long ull;

// ---- scratch (__device__ globals; no allocation allowed) ----
__device__ __nv_bfloat16 g_Qb[BATCH * NH * S_LEN * 64];  // [hi(32)|lo(32)] bf16, scaled LOG2E/sqrt(32)
__device__ __nv_bfloat16 g_Kb[BATCH * NH * S_LEN * 64];  // [hi|lo] bf16
__device__ __nv_bfloat16 g_Vb[BATCH * NH * S_LEN * 64];  // [hi|lo] bf16
__device__ __half g_Xs  [BATCH * S_LEN * KTOT];          // x        -> fp16
__device__ __half g_Os  [BATCH * S_LEN * KTOT];          // attn out -> fp16
__device__ __half g_Win2 [3 * EDIM * KTOT];              // in_proj_w -> fp16
__device__ __half g_Wout2[EDIM * KTOT];                  // out_w     -> fp16

// ============================ helpers ============================
__device__ __forceinline__ uint32_t smem_u32(const void* p) {
    uint32_t a;
    asm("{ .reg .u64 t; cvta.to.shared.u64 t, %1; cvt.u32.u64 %0, t; }" : "=r"(a) : "l"(p));
    return a;
}
__device__ __forceinline__ uint32_t sw128(uint32_t off) {
    return off ^ ((off >> 3) & 0x70);
}
__device__ __forceinline__ void ldmx4(uint32_t& r0, uint32_t& r1, uint32_t& r2, uint32_t& r3,
                                      uint32_t addr) {
    asm volatile("ldmatrix.sync.aligned.m8n8.x4.shared.b16 {%0,%1,%2,%3}, [%4];"
                 : "=r"(r0), "=r"(r1), "=r"(r2), "=r"(r3) : "r"(addr));
}
__device__ __forceinline__ void ldmx4t(uint32_t& r0, uint32_t& r1, uint32_t& r2, uint32_t& r3,
                                       uint32_t addr) {
    asm volatile("ldmatrix.sync.aligned.m8n8.x4.trans.shared.b16 {%0,%1,%2,%3}, [%4];"
                 : "=r"(r0), "=r"(r1), "=r"(r2), "=r"(r3) : "r"(addr));
}
// bf16 mma (attention)
__device__ __forceinline__ void mma16816(float* c, const uint32_t* a, const uint32_t* b) {
    asm volatile(
        "mma.sync.aligned.m16n8k16.row.col.f32.bf16.bf16.f32 "
        "{%0,%1,%2,%3}, {%4,%5,%6,%7}, {%8,%9}, {%0,%1,%2,%3};"
        : "+f"(c[0]), "+f"(c[1]), "+f"(c[2]), "+f"(c[3])
        : "r"(a[0]), "r"(a[1]), "r"(a[2]), "r"(a[3]), "r"(b[0]), "r"(b[1]));
}
// fp16 mma (projections)
__device__ __forceinline__ void mma16816h(float* c, const uint32_t* a, const uint32_t* b) {
    asm volatile(
        "mma.sync.aligned.m16n8k16.row.col.f32.f16.f16.f32 "
        "{%0,%1,%2,%3}, {%4,%5,%6,%7}, {%8,%9}, {%0,%1,%2,%3};"
        : "+f"(c[0]), "+f"(c[1]), "+f"(c[2]), "+f"(c[3])
        : "r"(a[0]), "r"(a[1]), "r"(a[2]), "r"(a[3]), "r"(b[0]), "r"(b[1]));
}
__device__ __forceinline__ float ex2(float x) {
    float y; asm("ex2.approx.ftz.f32 %0, %1;" : "=f"(y) : "f"(x)); return y;
}
__device__ __forceinline__ uint32_t cvt2(float a, float b) {
    uint32_t r; asm("cvt.rn.bf16x2.f32 %0, %1, %2;" : "=r"(r) : "f"(a), "f"(b)); return r;
}

// ============================ fused conversion kernel ============================
// One launch converts x, in_proj_w, out_w to fp16 (4 floats / thread).
#define N1Q (BATCH * S_LEN * EDIM / 4)   // 524288
#define N2Q (3 * EDIM * EDIM / 4)        // 49152
#define N3Q (EDIM * EDIM / 4)            // 16384

__global__ __launch_bounds__(256) void conv_all(const float* __restrict__ x,
                                                const float* __restrict__ w1,
                                                const float* __restrict__ w2) {
    int i = blockIdx.x * 256 + threadIdx.x;
    const float4* src;
    __half* dst;
    int off;
    if (i < N1Q)            { src = (const float4*)x;  dst = g_Xs;   off = i; }
    else if (i < N1Q + N2Q) { src = (const float4*)w1; dst = g_Win2; off = i - N1Q; }
    else                    { src = (const float4*)w2; dst = g_Wout2; off = i - N1Q - N2Q; }
    float4 v = src[off];
    __half2 a = __floats2half2_rn(v.x, v.y);
    __half2 b = __floats2half2_rn(v.z, v.w);
    uint2 u;
    u.x = *reinterpret_cast<uint32_t*>(&a);
    u.y = *reinterpret_cast<uint32_t*>(&b);
    *reinterpret_cast<uint2*>(dst + (size_t)off * 4) = u;
}

// ============================ fp16 HMMA GEMM (3-stage cp.async) ============================
#define GEMM_SMEM (3 * 32768)

template <int MODE>
__global__ __launch_bounds__(256, 2) void hgemm(
    const __half* __restrict__ A, const __half* __restrict__ B,
    const float* __restrict__ bias, float* __restrict__ C)
{
    extern __shared__ __align__(16) unsigned char dsm[];
    __shared__ float sbias[TN];
    const uint32_t sbase = smem_u32(dsm);

    const int tid = threadIdx.x, lane = tid & 31, wid = tid >> 5;
    const int warp_m = wid >> 2;
    const int warp_n = wid & 3;
    const int m0 = blockIdx.y * TM, n0 = blockIdx.x * TN;

    if (tid < TN) sbias[tid] = bias[n0 + tid];

    float acc[4][4][4];
#pragma unroll
    for (int i = 0; i < 4; i++)
#pragma unroll
        for (int j = 0; j < 4; j++)
#pragma unroll
            for (int e = 0; e < 4; e++) acc[i][j][e] = 0.f;

    const int r_ld = tid >> 3, c16 = tid & 7;
    const char* gA0 = (const char*)(A + (size_t)m0 * KTOT) + (size_t)r_ld * (KTOT * 2) + c16 * 16;
    const char* gB0 = (const char*)(B + (size_t)n0 * KTOT) + (size_t)r_ld * (KTOT * 2) + c16 * 16;

    const int arow = warp_m * 64 + (lane & 15);
    const int akb  = (lane >> 4) * 16;
    const int brow4 = warp_n * 32 + ((lane >> 4) << 3) + (lane & 7);
    const int bkb4  = ((lane >> 3) & 1) * 16;

#define ISSUE_CHUNK(ch, buf)                                                         \
    do {                                                                             \
        uint32_t dA = sbase + (buf) * 32768;                                         \
        uint32_t dB = dA + 16384;                                                    \
        const char* ga = gA0 + (ch) * 128;                                           \
        const char* gb = gB0 + (ch) * 128;                                           \
        _Pragma("unroll")                                                            \
        for (int i = 0; i < 4; i++) {                                                \
            uint32_t sw = sw128((r_ld + i * 32) * 128 + c16 * 16);                   \
            asm volatile("cp.async.cg.shared.global [%0], [%1], 16;"                 \
                         :: "r"(dA + sw), "l"(ga + (size_t)i * 32 * (KTOT * 2)));    \
            asm volatile("cp.async.cg.shared.global [%0], [%1], 16;"                 \
                         :: "r"(dB + sw), "l"(gb + (size_t)i * 32 * (KTOT * 2)));    \
        }                                                                            \
        asm volatile("cp.async.commit_group;" ::: "memory");                         \
    } while (0)

    ISSUE_CHUNK(0, 0);
    ISSUE_CHUNK(1, 1);

#pragma unroll
    for (int ch = 0; ch < NCHUNK; ch++) {
        if (ch + 1 < NCHUNK)
            asm volatile("cp.async.wait_group 1;" ::: "memory");
        else
            asm volatile("cp.async.wait_group 0;" ::: "memory");
        __syncthreads();
        if (ch + 2 < NCHUNK) ISSUE_CHUNK(ch + 2, (ch + 2) % 3);

        const uint32_t sA = sbase + (ch % 3) * 32768;
        const uint32_t sB = sA + 16384;
#pragma unroll
        for (int k16 = 0; k16 < 4; k16++) {
            uint32_t a[4][4], b[4][2];
#pragma unroll
            for (int mt = 0; mt < 4; mt++) {
                uint32_t addr = sA + sw128((arow + mt * 16) * 128 + k16 * 32 + akb);
                ldmx4(a[mt][0], a[mt][1], a[mt][2], a[mt][3], addr);
            }
#pragma unroll
            for (int np = 0; np < 2; np++) {
                uint32_t addr = sB + sw128((brow4 + np * 16) * 128 + k16 * 32 + bkb4);
                ldmx4(b[2 * np][0], b[2 * np][1], b[2 * np + 1][0], b[2 * np + 1][1], addr);
            }
#pragma unroll
            for (int mt = 0; mt < 4; mt++)
#pragma unroll
                for (int nt = 0; nt < 4; nt++)
                    mma16816h(acc[mt][nt], a[mt], b[nt]);
        }
    }
#undef ISSUE_CHUNK

    // ============ single-pass epilogue: full 128x132 fp32 stage (67.5KB) ============
    float* stage = reinterpret_cast<float*>(dsm);
    const int b_idx = m0 >> 12;
    const int which = n0 >> 8;
    const float sc = (MODE == 1 && which == 0) ? 0.2550348772f : 1.0f;  // LOG2E/sqrt(32)

    __syncthreads();   // all smem reads of last chunk complete
#pragma unroll
    for (int mt = 0; mt < 4; mt++) {
        int r0 = warp_m * 64 + mt * 16 + (lane >> 2);
#pragma unroll
        for (int nt = 0; nt < 4; nt++) {
            int cc = warp_n * 32 + nt * 8 + (lane & 3) * 2;
            *reinterpret_cast<float2*>(&stage[r0 * 132 + cc]) =
                make_float2(acc[mt][nt][0], acc[mt][nt][1]);
            *reinterpret_cast<float2*>(&stage[(r0 + 8) * 132 + cc]) =
                make_float2(acc[mt][nt][2], acc[mt][nt][3]);
        }
    }
    __syncthreads();
#pragma unroll
    for (int i = 0; i < 16; i++) {
        int e = tid + 256 * i;                 // 0..4095
        int r = e >> 5, c4 = e & 31;           // row 0..127, float4 col 0..31
        float4 v;
        v.x = (stage[r * 132 + c4 * 4 + 0] + sbias[c4 * 4 + 0]) * sc;
        v.y = (stage[r * 132 + c4 * 4 + 1] + sbias[c4 * 4 + 1]) * sc;
        v.z = (stage[r * 132 + c4 * 4 + 2] + sbias[c4 * 4 + 2]) * sc;
        v.w = (stage[r * 132 + c4 * 4 + 3] + sbias[c4 * 4 + 3]) * sc;
        int grow = m0 + r;
        if (MODE == 1) {
            int f = n0 + c4 * 4;
            int hh = (f >> 5) & 7, d0 = f & 31;
            __nv_bfloat16* dst = (which == 0) ? g_Qb : (which == 1) ? g_Kb : g_Vb;
            int s = grow & (S_LEN - 1);
            union { __nv_bfloat16 h[4]; ull u; } H, L;
            H.h[0] = __float2bfloat16(v.x); L.h[0] = __float2bfloat16(v.x - __bfloat162float(H.h[0]));
            H.h[1] = __float2bfloat16(v.y); L.h[1] = __float2bfloat16(v.y - __bfloat162float(H.h[1]));
            H.h[2] = __float2bfloat16(v.z); L.h[2] = __float2bfloat16(v.z - __bfloat162float(H.h[2]));
            H.h[3] = __float2bfloat16(v.w); L.h[3] = __float2bfloat16(v.w - __bfloat162float(H.h[3]));
            __nv_bfloat16* p = dst + ((size_t)(b_idx * NH + hh) * S_LEN + s) * 64 + d0;
            *reinterpret_cast<ull*>(p)      = H.u;
            *reinterpret_cast<ull*>(p + 32) = L.u;
        } else {
            *reinterpret_cast<float4*>(C + (size_t)grow * EDIM + n0 + c4 * 4) = v;
        }
    }
}

// ============================ banded attention (bf16-split HMMA flash) ============================
#define RP 144                                           // smem row pitch (bytes)
#define AT_SMEM (256 * RP + 256 * RP + 128 * RP)         // K + V + Q = 92160

__global__ __launch_bounds__(256, 2) void attn_mma()
{
    extern __shared__ __align__(16) unsigned char asmem[];
    unsigned char* sK = asmem;
    unsigned char* sV = asmem + 256 * RP;
    unsigned char* sQ = asmem + 2 * 256 * RP;
    const uint32_t uK = smem_u32(sK), uV = smem_u32(sV), uQ = smem_u32(sQ);

    const int t = threadIdx.x, lane = t & 31, w = t >> 5;
    const int q0 = blockIdx.x * 128, h = blockIdx.y, b = blockIdx.z;
    const size_t bh = (size_t)(b * NH + h) * S_LEN;
    const char* Kg = (const char*)(g_Kb + bh * 64);
    const char* Vg = (const char*)(g_Vb + bh * 64);
    const char* Qg = (const char*)(g_Qb + bh * 64);

#pragma unroll
    for (int i = 0; i < 8; i++) {
        int idx = t + 256 * i, r = idx >> 3, c = idx & 7;
        int j = q0 - 64 + r; j = j < 0 ? 0 : (j > S_LEN - 1 ? S_LEN - 1 : j);
        asm volatile("cp.async.cg.shared.global [%0], [%1], 16;"
                     :: "r"(uK + r * RP + c * 16), "l"(Kg + (size_t)j * 128 + c * 16));
        asm volatile("cp.async.cg.shared.global [%0], [%1], 16;"
                     :: "r"(uV + r * RP + c * 16), "l"(Vg + (size_t)j * 128 + c * 16));
    }
#pragma unroll
    for (int i = 0; i < 4; i++) {
        int idx = t + 256 * i, r = idx >> 3, c = idx & 7;
        asm volatile("cp.async.cg.shared.global [%0], [%1], 16;"
                     :: "r"(uQ + r * RP + c * 16), "l"(Qg + (size_t)(q0 + r) * 128 + c * 16));
    }
    asm volatile("cp.async.commit_group;" ::: "memory");
    asm volatile("cp.async.wait_group 0;" ::: "memory");
    __syncthreads();

    uint32_t aQ[4][4];
    {
        uint32_t base = uQ + (16 * w + (lane & 15)) * RP + (lane >> 4) * 16;
#pragma unroll
        for (int ks = 0; ks < 4; ks++)
            ldmx4(aQ[ks][0], aQ[ks][1], aQ[ks][2], aQ[ks][3], base + ks * 32);
    }

    float S[18][4];
#pragma unroll
    for (int nt = 0; nt < 18; nt++)
#pragma unroll
        for (int e = 0; e < 4; e++) S[nt][e] = 0.f;
    {
        uint32_t kb4 = uK + (16 * w + ((lane >> 4) << 3) + (lane & 7)) * RP
                     + ((lane >> 3) & 1) * 16;
#pragma unroll
        for (int ntp = 0; ntp < 9; ntp++) {
            uint32_t ad = kb4 + ntp * 16 * RP;
            uint32_t h0[4], h1[4], l0[4], l1[4];
            ldmx4(h0[0], h0[1], h0[2], h0[3], ad);
            ldmx4(h1[0], h1[1], h1[2], h1[3], ad + 32);
            ldmx4(l0[0], l0[1], l0[2], l0[3], ad + 64);
            ldmx4(l1[0], l1[1], l1[2], l1[3], ad + 96);
            float* s0 = S[2 * ntp];
            float* s1 = S[2 * ntp + 1];
            mma16816(s0, aQ[0], h0);     mma16816(s1, aQ[0], h0 + 2);
            mma16816(s0, aQ[1], h1);     mma16816(s1, aQ[1], h1 + 2);
            mma16816(s0, aQ[0], l0);     mma16816(s1, aQ[0], l0 + 2);
            mma16816(s0, aQ[1], l1);     mma16816(s1, aQ[1], l1 + 2);
            mma16816(s0, aQ[2], h0);     mma16816(s1, aQ[2], h0 + 2);
            mma16816(s0, aQ[3], h1);     mma16816(s1, aQ[3], h1 + 2);
        }
    }

    const int gid = lane >> 2, tig = lane & 3;
    const int jwb = q0 - 64 + 16 * w;
    float l0s = 0.f, l1s = 0.f;
    uint32_t Ph[18][2], Pl[18][2];
#pragma unroll
    for (int nt = 0; nt < 18; nt++) {
        int c0 = 8 * nt + 2 * tig, c1 = c0 + 1;
        int jg0 = jwb + c0, jg1 = jg0 + 1;
        bool in0 = (jg0 >= 0) && (jg0 < S_LEN);
        bool in1 = (jg1 >= 0) && (jg1 < S_LEN);
        bool v00 = in0 && (c0 >= gid)     && (c0 <= gid + 128);
        bool v01 = in1 && (c1 >= gid)     && (c1 <= gid + 128);
        bool v10 = in0 && (c0 >= gid + 8) && (c0 <= gid + 136);
        bool v11 = in1 && (c1 >= gid + 8) && (c1 <= gid + 136);
        float e00 = v00 ? ex2(S[nt][0]) : 0.f;
        float e01 = v01 ? ex2(S[nt][1]) : 0.f;
        float e10 = v10 ? ex2(S[nt][2]) : 0.f;
        float e11 = v11 ? ex2(S[nt][3]) : 0.f;
        l0s += e00 + e01; l1s += e10 + e11;
        uint32_t ph0 = cvt2(e01, e00);
        uint32_t ph1 = cvt2(e11, e10);
        Ph[nt][0] = ph0; Ph[nt][1] = ph1;
        float pl00 = e00 - __uint_as_float(ph0 << 16);
        float pl01 = e01 - __uint_as_float(ph0 & 0xFFFF0000u);
        float pl10 = e10 - __uint_as_float(ph1 << 16);
        float pl11 = e11 - __uint_as_float(ph1 & 0xFFFF0000u);
        Pl[nt][0] = cvt2(pl01, pl00);
        Pl[nt][1] = cvt2(pl11, pl10);
    }

    float O[8][4];
#pragma unroll
    for (int nt = 0; nt < 8; nt++)
#pragma unroll
        for (int e = 0; e < 4; e++) O[nt][e] = 0.f;
    {
        uint32_t vb4 = uV + (16 * w + (lane & 15)) * RP + (lane >> 4) * 16;
#pragma unroll
        for (int kk = 0; kk < 9; kk++) {
            uint32_t aH[4] = {Ph[2 * kk][0], Ph[2 * kk][1], Ph[2 * kk + 1][0], Ph[2 * kk + 1][1]};
            uint32_t aL[4] = {Pl[2 * kk][0], Pl[2 * kk][1], Pl[2 * kk + 1][0], Pl[2 * kk + 1][1]};
            uint32_t rad = vb4 + kk * 16 * RP;
#pragma unroll
            for (int nt2 = 0; nt2 < 4; nt2++) {
                uint32_t v4[4];
                ldmx4t(v4[0], v4[1], v4[2], v4[3], rad + nt2 * 32);
                mma16816(O[2 * nt2],     aH, v4);
                mma16816(O[2 * nt2 + 1], aH, v4 + 2);
                if (nt2 < 2) {
                    mma16816(O[2 * nt2],     aL, v4);
                    mma16816(O[2 * nt2 + 1], aL, v4 + 2);
                }
            }
        }
    }

    l0s += __shfl_xor_sync(0xffffffffu, l0s, 1);
    l0s += __shfl_xor_sync(0xffffffffu, l0s, 2);
    l1s += __shfl_xor_sync(0xffffffffu, l1s, 1);
    l1s += __shfl_xor_sync(0xffffffffu, l1s, 2);
    const float inv0 = 1.f / l0s, inv1 = 1.f / l1s;

    float* stg = reinterpret_cast<float*>(sQ);
#pragma unroll
    for (int nt = 0; nt < 4; nt++) {
        float o0 = (O[nt][0] + O[nt + 4][0]) * inv0;
        float o1 = (O[nt][1] + O[nt + 4][1]) * inv0;
        float o2 = (O[nt][2] + O[nt + 4][2]) * inv1;
        float o3 = (O[nt][3] + O[nt + 4][3]) * inv1;
        int r0 = 16 * w + gid;
        *reinterpret_cast<float2*>(stg + r0 * 36 + 8 * nt + 2 * tig) = make_float2(o0, o1);
        *reinterpret_cast<float2*>(stg + (r0 + 8) * 36 + 8 * nt + 2 * tig) = make_float2(o2, o3);
    }
    __syncthreads();

    const int m_base = b * S_LEN + q0;
#pragma unroll
    for (int i = 0; i < 2; i++) {
        int e = t + 256 * i, r = e >> 2, c8 = e & 3;
        union { __half v[8]; uint4 u; } H;
#pragma unroll
        for (int jj = 0; jj < 8; jj++)
            H.v[jj] = __float2half_rn(stg[r * 36 + c8 * 8 + jj]);
        __half* orow = g_Os + (size_t)(m_base + r) * KTOT + h * HD + c8 * 8;
        *reinterpret_cast<uint4*>(orow) = H.u;
    }
}

// ============================ launch ============================
extern "C" void kernel_launch(void* const* d_in, const int* in_sizes, int n_in,
                              void* d_out, int out_size)
{
    const float* x    = (const float*)d_in[0];   // [2,4096,256]
    const float* in_w = (const float*)d_in[1];   // [768,256]
    const float* in_b = (const float*)d_in[2];   // [768]
    const float* ow   = (const float*)d_in[3];   // [256,256]
    const float* ob   = (const float*)d_in[4];   // [256]
    float* out = (float*)d_out;                  // [2,4096,256]

    __half *Xs, *Os, *Win2, *Wout2;
    cudaGetSymbolAddress((void**)&Xs,    g_Xs);
    cudaGetSymbolAddress((void**)&Os,    g_Os);
    cudaGetSymbolAddress((void**)&Win2,  g_Win2);
    cudaGetSymbolAddress((void**)&Wout2, g_Wout2);

    cudaFuncSetAttribute(hgemm<1>, cudaFuncAttributeMaxDynamicSharedMemorySize, GEMM_SMEM);
    cudaFuncSetAttribute(hgemm<0>, cudaFuncAttributeMaxDynamicSharedMemorySize, GEMM_SMEM);
    cudaFuncSetAttribute(attn_mma, cudaFuncAttributeMaxDynamicSharedMemorySize, AT_SMEM);

    // 0) fused fp16 conversions (one launch)
    conv_all<<<(N1Q + N2Q + N3Q) / 256, 256>>>(x, in_w, ow);

    // 1) QKV projection (fp16 HMMA, K=256) -> g_Qb/g_Kb/g_Vb (bf16 split, Q pre-scaled)
    {
        dim3 grid(3 * EDIM / TN, BATCH * S_LEN / TM);   // (6, 64)
        hgemm<1><<<grid, 256, GEMM_SMEM>>>(Xs, Win2, in_b, nullptr);
    }

    // 2) banded flash attention (bf16 HMMA) -> g_Os (fp16)
    {
        dim3 grid(S_LEN / 128, NH, BATCH);              // (32, 8, 2)
        attn_mma<<<grid, 256, AT_SMEM>>>();
    }

    // 3) output projection (fp16 HMMA, K=256) -> out
    {
        dim3 grid(EDIM / TN, BATCH * S_LEN / TM);       // (2, 64)
        hgemm<0><<<grid, 256, GEMM_SMEM>>>(Os, Wout2, ob, out);
    }
}

// round 12
// speedup vs baseline: 7.9883x; 1.1706x over previous
#include <cuda_runtime.h>
#include <cuda_fp16.h>
#include <math.h>
#include <stdint.h>

#define S_LEN  4096
#define BATCH  2
#define NH     8
#define HD     32
#define EDIM   256
#define WIN    64

#define KTOT   256        // plain fp16 GEMM K
#define CH     64
#define NCHUNK (KTOT / CH)
#define TM     64
#define TN     128

typedef unsigned long long ull;

// ---- scratch (__device__ globals; no allocation allowed) ----
__device__ __half g_Qh[BATCH * NH * S_LEN * HD];   // fp16, scaled LOG2E/sqrt(32)
__device__ __half g_Kh[BATCH * NH * S_LEN * HD];   // fp16
__device__ __half g_Vh[BATCH * NH * S_LEN * HD];   // fp16
__device__ __half g_Xs  [BATCH * S_LEN * KTOT];    // x        -> fp16
__device__ __half g_Os  [BATCH * S_LEN * KTOT];    // attn out -> fp16
__device__ __half g_Win2 [3 * EDIM * KTOT];        // in_proj_w -> fp16
__device__ __half g_Wout2[EDIM * KTOT];            // out_w     -> fp16

// ============================ helpers ============================
__device__ __forceinline__ uint32_t smem_u32(const void* p) {
    uint32_t a;
    asm("{ .reg .u64 t; cvta.to.shared.u64 t, %1; cvt.u32.u64 %0, t; }" : "=r"(a) : "l"(p));
    return a;
}
__device__ __forceinline__ uint32_t sw128(uint32_t off) {
    return off ^ ((off >> 3) & 0x70);
}
__device__ __forceinline__ void ldmx4(uint32_t& r0, uint32_t& r1, uint32_t& r2, uint32_t& r3,
                                      uint32_t addr) {
    asm volatile("ldmatrix.sync.aligned.m8n8.x4.shared.b16 {%0,%1,%2,%3}, [%4];"
                 : "=r"(r0), "=r"(r1), "=r"(r2), "=r"(r3) : "r"(addr));
}
__device__ __forceinline__ void ldmx4t(uint32_t& r0, uint32_t& r1, uint32_t& r2, uint32_t& r3,
                                       uint32_t addr) {
    asm volatile("ldmatrix.sync.aligned.m8n8.x4.trans.shared.b16 {%0,%1,%2,%3}, [%4];"
                 : "=r"(r0), "=r"(r1), "=r"(r2), "=r"(r3) : "r"(addr));
}
// fp16 mma
__device__ __forceinline__ void mma16816h(float* c, const uint32_t* a, const uint32_t* b) {
    asm volatile(
        "mma.sync.aligned.m16n8k16.row.col.f32.f16.f16.f32 "
        "{%0,%1,%2,%3}, {%4,%5,%6,%7}, {%8,%9}, {%0,%1,%2,%3};"
        : "+f"(c[0]), "+f"(c[1]), "+f"(c[2]), "+f"(c[3])
        : "r"(a[0]), "r"(a[1]), "r"(a[2]), "r"(a[3]), "r"(b[0]), "r"(b[1]));
}
__device__ __forceinline__ float ex2(float x) {
    float y; asm("ex2.approx.ftz.f32 %0, %1;" : "=f"(y) : "f"(x)); return y;
}
// d = {hi = f16(a), lo = f16(b)}
__device__ __forceinline__ uint32_t cvt2h(float a, float b) {
    uint32_t r; asm("cvt.rn.f16x2.f32 %0, %1, %2;" : "=r"(r) : "f"(a), "f"(b)); return r;
}

// ============================ fused conversion kernel ============================
#define N1Q (BATCH * S_LEN * EDIM / 4)   // 524288
#define N2Q (3 * EDIM * EDIM / 4)        // 49152
#define N3Q (EDIM * EDIM / 4)            // 16384

__global__ __launch_bounds__(256) void conv_all(const float* __restrict__ x,
                                                const float* __restrict__ w1,
                                                const float* __restrict__ w2) {
    int i = blockIdx.x * 256 + threadIdx.x;
    const float4* src;
    __half* dst;
    int off;
    if (i < N1Q)            { src = (const float4*)x;  dst = g_Xs;   off = i; }
    else if (i < N1Q + N2Q) { src = (const float4*)w1; dst = g_Win2; off = i - N1Q; }
    else                    { src = (const float4*)w2; dst = g_Wout2; off = i - N1Q - N2Q; }
    float4 v = src[off];
    __half2 a = __floats2half2_rn(v.x, v.y);
    __half2 b = __floats2half2_rn(v.z, v.w);
    uint2 u;
    u.x = *reinterpret_cast<uint32_t*>(&a);
    u.y = *reinterpret_cast<uint32_t*>(&b);
    *reinterpret_cast<uint2*>(dst + (size_t)off * 4) = u;
}

// ============================ fp16 HMMA GEMM (64x128 tile, 3-stage cp.async) ============================
// stage: A 64x128B (8KB) + B 128x128B (16KB) = 24KB; 3 stages = 72KB.
#define STAGE_BYTES 24576
#define GEMM_SMEM (3 * STAGE_BYTES)

template <int MODE>
__global__ __launch_bounds__(256, 2) void hgemm(
    const __half* __restrict__ A, const __half* __restrict__ B,
    const float* __restrict__ bias, float* __restrict__ C)
{
    extern __shared__ __align__(16) unsigned char dsm[];
    __shared__ float sbias[TN];
    const uint32_t sbase = smem_u32(dsm);

    const int tid = threadIdx.x, lane = tid & 31, wid = tid >> 5;
    const int warp_m = wid >> 2;          // 0..1 (32 rows each)
    const int warp_n = wid & 3;           // 0..3 (32 cols each)
    const int m0 = blockIdx.y * TM, n0 = blockIdx.x * TN;

    if (tid < TN) sbias[tid] = bias[n0 + tid];

    float acc[2][4][4];
#pragma unroll
    for (int i = 0; i < 2; i++)
#pragma unroll
        for (int j = 0; j < 4; j++)
#pragma unroll
            for (int e = 0; e < 4; e++) acc[i][j][e] = 0.f;

    const int r_ld = tid >> 3, c16 = tid & 7;   // row 0..31, 16B col 0..7
    const char* gA0 = (const char*)(A + (size_t)m0 * KTOT) + (size_t)r_ld * (KTOT * 2) + c16 * 16;
    const char* gB0 = (const char*)(B + (size_t)n0 * KTOT) + (size_t)r_ld * (KTOT * 2) + c16 * 16;

    const int akb  = (lane >> 4) * 16;
    const int brow4 = warp_n * 32 + ((lane >> 4) << 3) + (lane & 7);
    const int bkb4  = ((lane >> 3) & 1) * 16;

#define ISSUE_CHUNK(ch, buf)                                                         \
    do {                                                                             \
        uint32_t dA = sbase + (buf) * STAGE_BYTES;                                   \
        uint32_t dB = dA + 8192;                                                     \
        const char* ga = gA0 + (ch) * 128;                                           \
        const char* gb = gB0 + (ch) * 128;                                           \
        _Pragma("unroll")                                                            \
        for (int i = 0; i < 2; i++) {                                                \
            uint32_t sw = sw128((r_ld + i * 32) * 128 + c16 * 16);                   \
            asm volatile("cp.async.cg.shared.global [%0], [%1], 16;"                 \
                         :: "r"(dA + sw), "l"(ga + (size_t)i * 32 * (KTOT * 2)));    \
        }                                                                            \
        _Pragma("unroll")                                                            \
        for (int i = 0; i < 4; i++) {                                                \
            uint32_t sw = sw128((r_ld + i * 32) * 128 + c16 * 16);                   \
            asm volatile("cp.async.cg.shared.global [%0], [%1], 16;"                 \
                         :: "r"(dB + sw), "l"(gb + (size_t)i * 32 * (KTOT * 2)));    \
        }                                                                            \
        asm volatile("cp.async.commit_group;" ::: "memory");                         \
    } while (0)

    ISSUE_CHUNK(0, 0);
    ISSUE_CHUNK(1, 1);

#pragma unroll
    for (int ch = 0; ch < NCHUNK; ch++) {
        if (ch + 1 < NCHUNK)
            asm volatile("cp.async.wait_group 1;" ::: "memory");
        else
            asm volatile("cp.async.wait_group 0;" ::: "memory");
        __syncthreads();
        if (ch + 2 < NCHUNK) ISSUE_CHUNK(ch + 2, (ch + 2) % 3);

        const uint32_t sA = sbase + (ch % 3) * STAGE_BYTES;
        const uint32_t sB = sA + 8192;
#pragma unroll
        for (int k16 = 0; k16 < 4; k16++) {
            uint32_t a[2][4], b[4][2];
#pragma unroll
            for (int mt = 0; mt < 2; mt++) {
                uint32_t addr = sA + sw128((warp_m * 32 + mt * 16 + (lane & 15)) * 128
                                           + k16 * 32 + akb);
                ldmx4(a[mt][0], a[mt][1], a[mt][2], a[mt][3], addr);
            }
#pragma unroll
            for (int np = 0; np < 2; np++) {
                uint32_t addr = sB + sw128((brow4 + np * 16) * 128 + k16 * 32 + bkb4);
                ldmx4(b[2 * np][0], b[2 * np][1], b[2 * np + 1][0], b[2 * np + 1][1], addr);
            }
#pragma unroll
            for (int mt = 0; mt < 2; mt++)
#pragma unroll
                for (int nt = 0; nt < 4; nt++)
                    mma16816h(acc[mt][nt], a[mt], b[nt]);
        }
    }
#undef ISSUE_CHUNK

    // ============ single-pass epilogue: 64x132 fp32 stage ============
    float* stage = reinterpret_cast<float*>(dsm);
    const int b_idx = m0 >> 12;
    const int which = n0 >> 8;
    const float sc = (MODE == 1 && which == 0) ? 0.2550348772f : 1.0f;  // LOG2E/sqrt(32)

    __syncthreads();
#pragma unroll
    for (int mt = 0; mt < 2; mt++) {
        int r0 = warp_m * 32 + mt * 16 + (lane >> 2);
#pragma unroll
        for (int nt = 0; nt < 4; nt++) {
            int cc = warp_n * 32 + nt * 8 + (lane & 3) * 2;
            *reinterpret_cast<float2*>(&stage[r0 * 132 + cc]) =
                make_float2(acc[mt][nt][0], acc[mt][nt][1]);
            *reinterpret_cast<float2*>(&stage[(r0 + 8) * 132 + cc]) =
                make_float2(acc[mt][nt][2], acc[mt][nt][3]);
        }
    }
    __syncthreads();
#pragma unroll
    for (int i = 0; i < 8; i++) {
        int e = tid + 256 * i;                 // 0..2047
        int r = e >> 5, c4 = e & 31;           // row 0..63, float4 col 0..31
        float4 v;
        v.x = (stage[r * 132 + c4 * 4 + 0] + sbias[c4 * 4 + 0]) * sc;
        v.y = (stage[r * 132 + c4 * 4 + 1] + sbias[c4 * 4 + 1]) * sc;
        v.z = (stage[r * 132 + c4 * 4 + 2] + sbias[c4 * 4 + 2]) * sc;
        v.w = (stage[r * 132 + c4 * 4 + 3] + sbias[c4 * 4 + 3]) * sc;
        int grow = m0 + r;
        if (MODE == 1) {
            int f = n0 + c4 * 4;
            int hh = (f >> 5) & 7, d0 = f & 31;
            __half* dst = (which == 0) ? g_Qh : (which == 1) ? g_Kh : g_Vh;
            int s = grow & (S_LEN - 1);
            union { __half h[4]; ull u; } H;
            H.h[0] = __float2half_rn(v.x);
            H.h[1] = __float2half_rn(v.y);
            H.h[2] = __float2half_rn(v.z);
            H.h[3] = __float2half_rn(v.w);
            *reinterpret_cast<ull*>(
                dst + ((size_t)(b_idx * NH + hh) * S_LEN + s) * HD + d0) = H.u;
        } else {
            *reinterpret_cast<float4*>(C + (size_t)grow * EDIM + n0 + c4 * 4) = v;
        }
    }
}

// ============================ banded attention (plain fp16 HMMA flash) ============================
// Block: 128 queries (8 warps x 16), key window 256 rows. Rows 64B fp16, pitch 80B.
#define RP 80
#define AT_SMEM (256 * RP + 256 * RP + 128 * RP)   // K + V + Q = 51200

__global__ __launch_bounds__(256, 2) void attn_mma()
{
    extern __shared__ __align__(16) unsigned char asmem[];
    unsigned char* sK = asmem;
    unsigned char* sV = asmem + 256 * RP;
    unsigned char* sQ = asmem + 2 * 256 * RP;
    const uint32_t uK = smem_u32(sK), uV = smem_u32(sV), uQ = smem_u32(sQ);

    const int t = threadIdx.x, lane = t & 31, w = t >> 5;
    const int q0 = blockIdx.x * 128, h = blockIdx.y, b = blockIdx.z;
    const size_t bh = (size_t)(b * NH + h) * S_LEN;
    const char* Kg = (const char*)(g_Kh + bh * HD);
    const char* Vg = (const char*)(g_Vh + bh * HD);
    const char* Qg = (const char*)(g_Qh + bh * HD);

    // async tile loads (rows = 64 bytes; clamp out-of-range keys, masked later)
#pragma unroll
    for (int i = 0; i < 4; i++) {
        int idx = t + 256 * i, r = idx >> 2, c = idx & 3;
        int j = q0 - 64 + r; j = j < 0 ? 0 : (j > S_LEN - 1 ? S_LEN - 1 : j);
        asm volatile("cp.async.cg.shared.global [%0], [%1], 16;"
                     :: "r"(uK + r * RP + c * 16), "l"(Kg + (size_t)j * 64 + c * 16));
        asm volatile("cp.async.cg.shared.global [%0], [%1], 16;"
                     :: "r"(uV + r * RP + c * 16), "l"(Vg + (size_t)j * 64 + c * 16));
    }
#pragma unroll
    for (int i = 0; i < 2; i++) {
        int idx = t + 256 * i, r = idx >> 2, c = idx & 3;
        asm volatile("cp.async.cg.shared.global [%0], [%1], 16;"
                     :: "r"(uQ + r * RP + c * 16), "l"(Qg + (size_t)(q0 + r) * 64 + c * 16));
    }
    asm volatile("cp.async.commit_group;" ::: "memory");
    asm volatile("cp.async.wait_group 0;" ::: "memory");
    __syncthreads();

    // Q a-frags: ksteps 0 (d0-15), 1 (d16-31)
    uint32_t aQ[2][4];
    {
        uint32_t base = uQ + (16 * w + (lane & 15)) * RP + (lane >> 4) * 16;
#pragma unroll
        for (int ks = 0; ks < 2; ks++)
            ldmx4(aQ[ks][0], aQ[ks][1], aQ[ks][2], aQ[ks][3], base + ks * 32);
    }

    // ---- QK: S[18 tiles][4], 9 nt-pairs, 2 LDSM + 4 MMA each ----
    float S[18][4];
#pragma unroll
    for (int nt = 0; nt < 18; nt++)
#pragma unroll
        for (int e = 0; e < 4; e++) S[nt][e] = 0.f;
    {
        uint32_t kb4 = uK + (16 * w + ((lane >> 4) << 3) + (lane & 7)) * RP
                     + ((lane >> 3) & 1) * 16;
#pragma unroll
        for (int ntp = 0; ntp < 9; ntp++) {
            uint32_t ad = kb4 + ntp * 16 * RP;
            uint32_t k0[4], k1[4];
            ldmx4(k0[0], k0[1], k0[2], k0[3], ad);        // d0-15, both n-tiles
            ldmx4(k1[0], k1[1], k1[2], k1[3], ad + 32);   // d16-31
            float* s0 = S[2 * ntp];
            float* s1 = S[2 * ntp + 1];
            mma16816h(s0, aQ[0], k0);   mma16816h(s1, aQ[0], k0 + 2);
            mma16816h(s0, aQ[1], k1);   mma16816h(s1, aQ[1], k1 + 2);
        }
    }

    // ---- mask + exp2 + row sums + P (fp16) ----
    const int gid = lane >> 2, tig = lane & 3;
    const int jwb = q0 - 64 + 16 * w;
    float l0s = 0.f, l1s = 0.f;
    uint32_t Ph[18][2];
#pragma unroll
    for (int nt = 0; nt < 18; nt++) {
        int c0 = 8 * nt + 2 * tig, c1 = c0 + 1;
        int jg0 = jwb + c0, jg1 = jg0 + 1;
        bool in0 = (jg0 >= 0) && (jg0 < S_LEN);
        bool in1 = (jg1 >= 0) && (jg1 < S_LEN);
        bool v00 = in0 && (c0 >= gid)     && (c0 <= gid + 128);
        bool v01 = in1 && (c1 >= gid)     && (c1 <= gid + 128);
        bool v10 = in0 && (c0 >= gid + 8) && (c0 <= gid + 136);
        bool v11 = in1 && (c1 >= gid + 8) && (c1 <= gid + 136);
        float e00 = v00 ? ex2(S[nt][0]) : 0.f;
        float e01 = v01 ? ex2(S[nt][1]) : 0.f;
        float e10 = v10 ? ex2(S[nt][2]) : 0.f;
        float e11 = v11 ? ex2(S[nt][3]) : 0.f;
        l0s += e00 + e01; l1s += e10 + e11;
        Ph[nt][0] = cvt2h(e01, e00);    // {lo=e00, hi=e01}
        Ph[nt][1] = cvt2h(e11, e10);
    }

    // ---- PV: O[4 tiles][4], 9 kk, 2 LDSM + 4 MMA each ----
    float O[4][4];
#pragma unroll
    for (int nt = 0; nt < 4; nt++)
#pragma unroll
        for (int e = 0; e < 4; e++) O[nt][e] = 0.f;
    {
        uint32_t vb4 = uV + (16 * w + (lane & 15)) * RP + (lane >> 4) * 16;
#pragma unroll
        for (int kk = 0; kk < 9; kk++) {
            uint32_t aH[4] = {Ph[2 * kk][0], Ph[2 * kk][1], Ph[2 * kk + 1][0], Ph[2 * kk + 1][1]};
            uint32_t rad = vb4 + kk * 16 * RP;
            uint32_t v0[4], v1[4];
            ldmx4t(v0[0], v0[1], v0[2], v0[3], rad);        // d0-15 -> tiles 0,1
            ldmx4t(v1[0], v1[1], v1[2], v1[3], rad + 32);   // d16-31 -> tiles 2,3
            mma16816h(O[0], aH, v0);   mma16816h(O[1], aH, v0 + 2);
            mma16816h(O[2], aH, v1);   mma16816h(O[3], aH, v1 + 2);
        }
    }

    // ---- normalize ----
    l0s += __shfl_xor_sync(0xffffffffu, l0s, 1);
    l0s += __shfl_xor_sync(0xffffffffu, l0s, 2);
    l1s += __shfl_xor_sync(0xffffffffu, l1s, 1);
    l1s += __shfl_xor_sync(0xffffffffu, l1s, 2);
    const float inv0 = 1.f / l0s, inv1 = 1.f / l1s;

    // stage fp32 (128 x 36 floats = 18KB, reuse sK region after sync)
    __syncthreads();
    float* stg = reinterpret_cast<float*>(sK);
#pragma unroll
    for (int nt = 0; nt < 4; nt++) {
        int r0 = 16 * w + gid;
        *reinterpret_cast<float2*>(stg + r0 * 36 + 8 * nt + 2 * tig) =
            make_float2(O[nt][0] * inv0, O[nt][1] * inv0);
        *reinterpret_cast<float2*>(stg + (r0 + 8) * 36 + 8 * nt + 2 * tig) =
            make_float2(O[nt][2] * inv1, O[nt][3] * inv1);
    }
    __syncthreads();

    // coalesced fp16 writes into g_Os
    const int m_base = b * S_LEN + q0;
#pragma unroll
    for (int i = 0; i < 2; i++) {
        int e = t + 256 * i, r = e >> 2, c8 = e & 3;
        union { __half v[8]; uint4 u; } H;
#pragma unroll
        for (int jj = 0; jj < 8; jj++)
            H.v[jj] = __float2half_rn(stg[r * 36 + c8 * 8 + jj]);
        __half* orow = g_Os + (size_t)(m_base + r) * KTOT + h * HD + c8 * 8;
        *reinterpret_cast<uint4*>(orow) = H.u;
    }
}

// ============================ launch ============================
extern "C" void kernel_launch(void* const* d_in, const int* in_sizes, int n_in,
                              void* d_out, int out_size)
{
    const float* x    = (const float*)d_in[0];   // [2,4096,256]
    const float* in_w = (const float*)d_in[1];   // [768,256]
    const float* in_b = (const float*)d_in[2];   // [768]
    const float* ow   = (const float*)d_in[3];   // [256,256]
    const float* ob   = (const float*)d_in[4];   // [256]
    float* out = (float*)d_out;                  // [2,4096,256]

    __half *Xs, *Os, *Win2, *Wout2;
    cudaGetSymbolAddress((void**)&Xs,    g_Xs);
    cudaGetSymbolAddress((void**)&Os,    g_Os);
    cudaGetSymbolAddress((void**)&Win2,  g_Win2);
    cudaGetSymbolAddress((void**)&Wout2, g_Wout2);

    cudaFuncSetAttribute(hgemm<1>, cudaFuncAttributeMaxDynamicSharedMemorySize, GEMM_SMEM);
    cudaFuncSetAttribute(hgemm<0>, cudaFuncAttributeMaxDynamicSharedMemorySize, GEMM_SMEM);
    cudaFuncSetAttribute(attn_mma, cudaFuncAttributeMaxDynamicSharedMemorySize, AT_SMEM);

    // 0) fused fp16 conversions (one launch)
    conv_all<<<(N1Q + N2Q + N3Q) / 256, 256>>>(x, in_w, ow);

    // 1) QKV projection (fp16 HMMA, 64x128 tiles) -> g_Qh/g_Kh/g_Vh
    {
        dim3 grid(3 * EDIM / TN, BATCH * S_LEN / TM);   // (6, 128) = 768 CTAs
        hgemm<1><<<grid, 256, GEMM_SMEM>>>(Xs, Win2, in_b, nullptr);
    }

    // 2) banded flash attention (fp16 HMMA) -> g_Os
    {
        dim3 grid(S_LEN / 128, NH, BATCH);              // (32, 8, 2) = 512 CTAs
        attn_mma<<<grid, 256, AT_SMEM>>>();
    }

    // 3) output projection (fp16 HMMA, 64x128 tiles) -> out
    {
        dim3 grid(EDIM / TN, BATCH * S_LEN / TM);       // (2, 128) = 256 CTAs
        hgemm<0><<<grid, 256, GEMM_SMEM>>>(Os, Wout2, ob, out);
    }
}